// round 15
// baseline (speedup 1.0000x reference)
#include <cuda_runtime.h>
#include <cuda_bf16.h>
#include <math.h>
#include <stdint.h>

// ---------------- problem constants ----------------
#define BB   32
#define LL   512
#define DDIM 192
#define DEPTH 12
#define HH   6
#define DHH  32
#define KCLIP 32
#define BINS 65
#define NROW (BB*LL)          // 16384
#define QKVN (3*DDIM)         // 576
#define FFN  (4*DDIM)         // 768
#define SCALE_Q 0.17677669529663687f

// ---------------- scratch ----------------
__device__ float g_x  [NROW*DDIM];
__device__ float g_maskf[NROW];
__device__ int   g_mask_is_u8;

// packed activation fragments (bf16 hi/lo words, mma-fragment layout)
#define APK_A_WORDS (NROW*DDIM/2)    // K=192 layout (NKB=12)
#define APK_B_WORDS (NROW*FFN/2)     // K=768 layout (NKB=48)
__device__ unsigned g_aA_hi[APK_A_WORDS], g_aA_lo[APK_A_WORDS];
__device__ unsigned g_aB_hi[APK_B_WORDS], g_aB_lo[APK_B_WORDS];

// packed attention inputs (per layer): Q/K row-major bf16-pair words per (b,h);
// V transposed: [(b*H+h)][d][p] word = (v[2p][d], v[2p+1][d])
#define PQW (BB*HH*LL*16)            // 1572864 words each
__device__ unsigned g_qp_hi[PQW], g_qp_lo[PQW];
__device__ unsigned g_kp_hi[PQW], g_kp_lo[PQW];
__device__ unsigned g_vp_hi[PQW], g_vp_lo[PQW];

// packed weight fragments, all layers
#define WPK_L4 55296                 // uint4 per layer (qkv+out+ff1+ff2)
#define OFF_QKV4 0
#define OFF_OUT4 13824
#define OFF_FF14 18432
#define OFF_FF24 36864
__device__ unsigned g_w_hi[WPK_L4*DEPTH*4], g_w_lo[WPK_L4*DEPTH*4];

// ---------------- mask handling ----------------
__global__ void mask_reset_kernel() { g_mask_is_u8 = 0; }
__global__ void mask_detect_kernel(const unsigned char* __restrict__ m) {
    int i = blockIdx.x * 256 + threadIdx.x;
    if (i < NROW && (i & 3) != 0 && m[i] != 0) atomicOr(&g_mask_is_u8, 1);
}
__global__ void mask_expand_kernel(const void* __restrict__ m) {
    int i = blockIdx.x * 256 + threadIdx.x;
    if (i >= NROW) return;
    int v;
    if (g_mask_is_u8) v = ((const unsigned char*)m)[i];
    else              v = ((const int*)m)[i];
    g_maskf[i] = v ? 1.0f : 0.0f;
}

// ---------------- embedding ----------------
__global__ void embed_kernel(const int* __restrict__ seq,
                             const float* __restrict__ emb,
                             float* __restrict__ x) {
    int i = blockIdx.x * 256 + threadIdx.x;
    if (i >= NROW * DDIM) return;
    int row = i / DDIM, c = i - row * DDIM;
    x[i] = emb[seq[row] * DDIM + c];
}

// ---------------- bf16 helpers ----------------
__device__ __forceinline__ unsigned pack_bf16(float lo, float hi) {
    unsigned r;
    asm("cvt.rn.bf16x2.f32 %0, %1, %2;" : "=r"(r) : "f"(hi), "f"(lo));
    return r;
}
__device__ __forceinline__ unsigned lo_residual(unsigned hiw, float lo, float hi) {
    float h0 = __uint_as_float(hiw << 16);
    float h1 = __uint_as_float(hiw & 0xffff0000u);
    return pack_bf16(lo - h0, hi - h1);
}
__device__ __forceinline__ void mma_bf16v(float* c,
                                          unsigned a0, unsigned a1, unsigned a2, unsigned a3,
                                          unsigned b0, unsigned b1) {
    asm("mma.sync.aligned.m16n8k16.row.col.f32.bf16.bf16.f32 "
        "{%0,%1,%2,%3},{%4,%5,%6,%7},{%8,%9},{%0,%1,%2,%3};"
        : "+f"(c[0]), "+f"(c[1]), "+f"(c[2]), "+f"(c[3])
        : "r"(a0), "r"(a1), "r"(a2), "r"(a3), "r"(b0), "r"(b1));
}

// ---------------- layernorm + fragment pack (warp per row) ----------------
__global__ void ln_pack_kernel(const float* __restrict__ x,
                               const float* __restrict__ s, const float* __restrict__ bb,
                               unsigned* __restrict__ hi, unsigned* __restrict__ lo) {
    int row  = blockIdx.x * 8 + (threadIdx.x >> 5);
    int lane = threadIdx.x & 31;
    const float* xr = x + (size_t)row * DDIM;
    float2 v[3]; float sum = 0.f;
#pragma unroll
    for (int jj = 0; jj < 3; jj++) {
        v[jj] = *reinterpret_cast<const float2*>(xr + 2 * (lane + 32 * jj));
        sum += v[jj].x + v[jj].y;
    }
#pragma unroll
    for (int o = 16; o; o >>= 1) sum += __shfl_xor_sync(0xffffffffu, sum, o);
    float mu = sum * (1.0f / DDIM);
    float vs = 0.f;
#pragma unroll
    for (int jj = 0; jj < 3; jj++) {
        float d0 = v[jj].x - mu, d1 = v[jj].y - mu;
        vs += d0 * d0 + d1 * d1;
    }
#pragma unroll
    for (int o = 16; o; o >>= 1) vs += __shfl_xor_sync(0xffffffffu, vs, o);
    float inv = rsqrtf(vs * (1.0f / DDIM) + 1e-5f);

    int m16 = row >> 4, g8 = row & 7, hi8 = (row >> 3) & 1;
#pragma unroll
    for (int jj = 0; jj < 3; jj++) {
        int p = lane + 32 * jj;
        int kb = p >> 3, tgp = p & 3, cw = (p >> 2) & 1;
        float2 sv = *reinterpret_cast<const float2*>(s + 2 * p);
        float2 bv = *reinterpret_cast<const float2*>(bb + 2 * p);
        float f0 = (v[jj].x - mu) * inv * sv.x + bv.x;
        float f1 = (v[jj].y - mu) * inv * sv.y + bv.y;
        unsigned hw = pack_bf16(f0, f1);
        int idx = ((m16 * 12 + kb) * 32 + g8 * 4 + tgp) * 4 + hi8 + 2 * cw;
        hi[idx] = hw;
        lo[idx] = lo_residual(hw, f0, f1);
    }
}

// ---------------- weight fragment pack (warp per (layer, n32, kb)) ----------------
__global__ void pack_w_kernel(const float* __restrict__ W, unsigned* __restrict__ hiW,
                              unsigned* __restrict__ loW, int N, int K, int dstBase4) {
    int wid  = blockIdx.x * 8 + (threadIdx.x >> 5);
    int lane = threadIdx.x & 31, g = lane >> 2, tg = lane & 3;
    int NKB = K >> 4, perL = (N >> 5) * NKB;
    if (wid >= DEPTH * perL) return;
    int l = wid / perL, rem = wid - l * perL;
    int n32 = rem / NKB, kb = rem - n32 * NKB;
    const float* Wl = W + (size_t)l * N * K;
    unsigned wh[8], wl[8];
#pragma unroll
    for (int j = 0; j < 4; j++) {
        int n = n32 * 32 + j * 8 + g;
        const float* p = Wl + (size_t)n * K + kb * 16;
        float2 u = *reinterpret_cast<const float2*>(p + 2 * tg);
        float2 q = *reinterpret_cast<const float2*>(p + 8 + 2 * tg);
        wh[j*2]   = pack_bf16(u.x, u.y);
        wl[j*2]   = lo_residual(wh[j*2], u.x, u.y);
        wh[j*2+1] = pack_bf16(q.x, q.y);
        wl[j*2+1] = lo_residual(wh[j*2+1], q.x, q.y);
    }
    size_t o4 = (size_t)l * WPK_L4 + dstBase4 + (size_t)(n32 * NKB + kb) * 64 + lane;
    uint4* H = reinterpret_cast<uint4*>(hiW);
    uint4* L = reinterpret_cast<uint4*>(loW);
    H[o4]      = make_uint4(wh[0], wh[1], wh[2], wh[3]);
    H[o4 + 32] = make_uint4(wh[4], wh[5], wh[6], wh[7]);
    L[o4]      = make_uint4(wl[0], wl[1], wl[2], wl[3]);
    L[o4 + 32] = make_uint4(wl[4], wl[5], wl[6], wl[7]);
}

// ================= fragment-direct GEMM (no smem, no syncs) =================
// MODE 1: C=acc+bias+res (fp32)   MODE 2: gelu(acc+bias) -> packed (Phi/Plo)
// MODE 3: QKV -> packed Q (scaled)/K row-major words + V transposed words
template <int MODE>
__global__ __launch_bounds__(256, 2)
void gemm_pk_kernel(const unsigned* __restrict__ AhiW, const unsigned* __restrict__ AloW,
                    const unsigned* __restrict__ BhiW, const unsigned* __restrict__ BloW,
                    const float* __restrict__ bias, const float* __restrict__ res,
                    float* __restrict__ C,
                    unsigned* __restrict__ Phi, unsigned* __restrict__ Plo,
                    unsigned* __restrict__ Khi, unsigned* __restrict__ Klo,
                    unsigned* __restrict__ Vhi, unsigned* __restrict__ Vlo,
                    int M, int N, int K, int NKB_OUT) {
    const uint4* Ahi = reinterpret_cast<const uint4*>(AhiW);
    const uint4* Alo = reinterpret_cast<const uint4*>(AloW);
    const uint4* Bhi = reinterpret_cast<const uint4*>(BhiW);
    const uint4* Blo = reinterpret_cast<const uint4*>(BloW);

    const int tid = threadIdx.x, lane = tid & 31, wid = tid >> 5;
    const int g = lane >> 2, tg = lane & 3;
    const int wm = (wid & 3) * 32, wn = (wid >> 2) * 32;
    const int m0 = blockIdx.y * 128, n0 = blockIdx.x * 64;
    const int NKB = K >> 4;
    const size_t m16a = (size_t)((m0 + wm) >> 4);
    const size_t n32  = (size_t)((n0 + wn) >> 5);

    const uint4* pa0h = Ahi + m16a * NKB * 32 + lane;
    const uint4* pa1h = Ahi + (m16a + 1) * NKB * 32 + lane;
    const uint4* pa0l = Alo + m16a * NKB * 32 + lane;
    const uint4* pa1l = Alo + (m16a + 1) * NKB * 32 + lane;
    const uint4* pbh  = Bhi + n32 * NKB * 64 + lane;
    const uint4* pbl  = Blo + n32 * NKB * 64 + lane;

    float acc[2][4][4];
#pragma unroll
    for (int i = 0; i < 2; i++)
#pragma unroll
        for (int j = 0; j < 4; j++)
#pragma unroll
            for (int t = 0; t < 4; t++) acc[i][j][t] = 0.f;

    uint4 cA0h = pa0h[0], cA1h = pa1h[0], cA0l = pa0l[0], cA1l = pa1l[0];
    uint4 cB0h = pbh[0], cB1h = pbh[32], cB0l = pbl[0], cB1l = pbl[32];

    for (int kb = 0; kb < NKB; kb++) {
        uint4 nA0h, nA1h, nA0l, nA1l, nB0h, nB1h, nB0l, nB1l;
        if (kb + 1 < NKB) {
            int off = (kb + 1) * 32, offb = (kb + 1) * 64;
            nA0h = pa0h[off]; nA1h = pa1h[off];
            nA0l = pa0l[off]; nA1l = pa1l[off];
            nB0h = pbh[offb]; nB1h = pbh[offb + 32];
            nB0l = pbl[offb]; nB1l = pbl[offb + 32];
        }
        unsigned aH[2][4] = {{cA0h.x, cA0h.y, cA0h.z, cA0h.w},
                             {cA1h.x, cA1h.y, cA1h.z, cA1h.w}};
        unsigned aL[2][4] = {{cA0l.x, cA0l.y, cA0l.z, cA0l.w},
                             {cA1l.x, cA1l.y, cA1l.z, cA1l.w}};
        unsigned bH[2][4] = {{cB0h.x, cB0h.y, cB0h.z, cB0h.w},
                             {cB1h.x, cB1h.y, cB1h.z, cB1h.w}};
        unsigned bL[2][4] = {{cB0l.x, cB0l.y, cB0l.z, cB0l.w},
                             {cB1l.x, cB1l.y, cB1l.z, cB1l.w}};
#pragma unroll
        for (int mf = 0; mf < 2; mf++) {
#pragma unroll
            for (int nf = 0; nf < 4; nf++) {
                unsigned b0 = bH[nf >> 1][(nf & 1) * 2];
                unsigned b1 = bH[nf >> 1][(nf & 1) * 2 + 1];
                unsigned l0 = bL[nf >> 1][(nf & 1) * 2];
                unsigned l1 = bL[nf >> 1][(nf & 1) * 2 + 1];
                mma_bf16v(acc[mf][nf], aH[mf][0], aH[mf][1], aH[mf][2], aH[mf][3], b0, b1);
                mma_bf16v(acc[mf][nf], aH[mf][0], aH[mf][1], aH[mf][2], aH[mf][3], l0, l1);
                mma_bf16v(acc[mf][nf], aL[mf][0], aL[mf][1], aL[mf][2], aL[mf][3], b0, b1);
            }
        }
        cA0h = nA0h; cA1h = nA1h; cA0l = nA0l; cA1l = nA1l;
        cB0h = nB0h; cB1h = nB1h; cB0l = nB0l; cB1l = nB1l;
    }

    if (MODE == 3) {
        // QKV packed epilogue. Warp's 32 columns = one head, one region.
        int cb = (n0 + wn) >> 5;          // 0..17
        int region = cb / HH;             // 0=q 1=k 2=v
        int h = cb - region * HH;
#pragma unroll
        for (int mf = 0; mf < 2; mf++) {
#pragma unroll
            for (int nf = 0; nf < 4; nf++) {
                int c = n0 + wn + nf * 8 + tg * 2;
                float2 bi = *reinterpret_cast<const float2*>(bias + c);
#pragma unroll
                for (int half = 0; half < 2; half++) {
                    int rr = m0 + wm + mf * 16 + g + half * 8;
                    float v0 = acc[mf][nf][half * 2 + 0] + bi.x;
                    float v1 = acc[mf][nf][half * 2 + 1] + bi.y;
                    int bidx = rr >> 9, row = rr & 511;
                    size_t bh = (size_t)(bidx * HH + h);
                    if (region == 0) {
                        v0 *= SCALE_Q; v1 *= SCALE_Q;
                        unsigned hw = pack_bf16(v0, v1);
                        size_t idx = (bh * 512 + row) * 16 + nf * 4 + tg;
                        Phi[idx] = hw;
                        Plo[idx] = lo_residual(hw, v0, v1);
                    } else if (region == 1) {
                        unsigned hw = pack_bf16(v0, v1);
                        size_t idx = (bh * 512 + row) * 16 + nf * 4 + tg;
                        Khi[idx] = hw;
                        Klo[idx] = lo_residual(hw, v0, v1);
                    } else {
                        float e0 = __shfl_xor_sync(0xffffffffu, v0, 4);
                        float e1 = __shfl_xor_sync(0xffffffffu, v1, 4);
                        if ((g & 1) == 0) {      // rr even; partner holds rr+1
                            int d = nf * 8 + tg * 2;
                            int p = row >> 1;
                            size_t i0 = (bh * 32 + d) * 256 + p;
                            unsigned w0 = pack_bf16(v0, e0);
                            unsigned w1 = pack_bf16(v1, e1);
                            Vhi[i0]       = w0;
                            Vlo[i0]       = lo_residual(w0, v0, e0);
                            Vhi[i0 + 256] = w1;
                            Vlo[i0 + 256] = lo_residual(w1, v1, e1);
                        }
                    }
                }
            }
        }
    } else if (MODE == 2) {
#pragma unroll
        for (int mf = 0; mf < 2; mf++) {
            int m16o = ((m0 + wm) >> 4) + mf;
#pragma unroll
            for (int nf = 0; nf < 4; nf++) {
                int c = n0 + wn + nf * 8 + tg * 2;
                float2 bi = *reinterpret_cast<const float2*>(bias + c);
                int kb2 = (n0 >> 4) + (wn >> 4) + (nf >> 1);
                int cw  = nf & 1;
#pragma unroll
                for (int half = 0; half < 2; half++) {
                    float v0 = acc[mf][nf][half * 2 + 0] + bi.x;
                    float v1 = acc[mf][nf][half * 2 + 1] + bi.y;
                    v0 = 0.5f * v0 * (1.0f + erff(v0 * 0.7071067811865476f));
                    v1 = 0.5f * v1 * (1.0f + erff(v1 * 0.7071067811865476f));
                    unsigned hw = pack_bf16(v0, v1);
                    int idx = ((m16o * NKB_OUT + kb2) * 32 + g * 4 + tg) * 4 + half + 2 * cw;
                    Phi[idx] = hw;
                    Plo[idx] = lo_residual(hw, v0, v1);
                }
            }
        }
    } else {
#pragma unroll
        for (int mf = 0; mf < 2; mf++) {
            int r = m0 + wm + mf * 16 + g;
#pragma unroll
            for (int nf = 0; nf < 4; nf++) {
                int c = n0 + wn + nf * 8 + tg * 2;
                float2 bi = *reinterpret_cast<const float2*>(bias + c);
#pragma unroll
                for (int half = 0; half < 2; half++) {
                    int rr = r + half * 8;
                    float v0 = acc[mf][nf][half * 2 + 0] + bi.x;
                    float v1 = acc[mf][nf][half * 2 + 1] + bi.y;
                    float2 rv = *reinterpret_cast<const float2*>(res + (size_t)rr * N + c);
                    v0 += rv.x; v1 += rv.y;
                    *reinterpret_cast<float2*>(C + (size_t)rr * N + c) = make_float2(v0, v1);
                }
            }
        }
    }
}

// ================= flash attention: copy-staging from packed inputs ==========
#define KQ_STRIDE 20
#define V_STRIDE  68
#define OFF_KH 0
#define OFF_KL 2560
#define OFF_QH 5120
#define OFF_QL 7680
#define OFF_VH 10240
#define OFF_VL 12416
#define OFF_LUT 14592
#define OFF_MSK (14592+1023)
#define SMEM_ATT_WORDS (14592+1023+512+9)
#define SMEM_ATT_BYTES (SMEM_ATT_WORDS*4)

__global__ __launch_bounds__(256, 2)
void attn_mma_kernel(const unsigned* __restrict__ qph, const unsigned* __restrict__ qpl,
                     const unsigned* __restrict__ kph, const unsigned* __restrict__ kpl,
                     const unsigned* __restrict__ vph, const unsigned* __restrict__ vpl,
                     const float* __restrict__ bppm,
                     const float* __restrict__ pair_w, const float* __restrict__ pair_b,
                     const float* __restrict__ relpos_w, const float* __restrict__ relpos_b,
                     unsigned* __restrict__ oHi, unsigned* __restrict__ oLo) {
    extern __shared__ unsigned sm[];
    unsigned* KsH = sm + OFF_KH;
    unsigned* KsL = sm + OFF_KL;
    unsigned* QsH = sm + OFF_QH;
    unsigned* QsL = sm + OFF_QL;
    unsigned* VsH = sm + OFF_VH;
    unsigned* VsL = sm + OFF_VL;
    float*    lut = (float*)(sm + OFF_LUT);
    float*    msk = (float*)(sm + OFF_MSK);

    const int tid  = threadIdx.x;
    const int lane = tid & 31;
    const int w    = tid >> 5;
    const int qt   = blockIdx.x;
    const int h    = blockIdx.y;
    const int b    = blockIdx.z;
    const int q0   = qt * 128;
    const int wq   = w * 16;
    const int g    = lane >> 2;
    const int tg   = lane & 3;
    const size_t bh = (size_t)(b * HH + h);

    // ---- stage Q (uint4 copy, already scaled/packed) ----
#pragma unroll
    for (int j = 0; j < 2; j++) {
        int id = j * 256 + tid;                 // 0..511
        int r = id >> 2, w4 = (id & 3) * 4;
        uint4 vh = *reinterpret_cast<const uint4*>(qph + (bh * 512 + q0 + r) * 16 + w4);
        uint4 vl = *reinterpret_cast<const uint4*>(qpl + (bh * 512 + q0 + r) * 16 + w4);
        *reinterpret_cast<uint4*>(QsH + r * KQ_STRIDE + w4) = vh;
        *reinterpret_cast<uint4*>(QsL + r * KQ_STRIDE + w4) = vl;
    }
    const float addc = pair_b[h] + relpos_b[h];
#pragma unroll
    for (int j = 0; j < 4; j++) {
        int i = j * 256 + tid;
        if (i < 1023) {
            int d = i - 511;
            int cd = min(KCLIP, max(-KCLIP, d)) + KCLIP;
            lut[i] = relpos_w[h * BINS + cd] + addc;
        }
    }
    for (int k = tid; k < LL; k += 256) msk[k] = g_maskf[b * LL + k];
    __syncthreads();

    unsigned qaH[2][4], qaL[2][4];
#pragma unroll
    for (int ks = 0; ks < 2; ks++) {
        int ab = (wq + g) * KQ_STRIDE + ks * 8 + tg;
        qaH[ks][0] = QsH[ab];       qaH[ks][1] = QsH[ab + 8 * KQ_STRIDE];
        qaH[ks][2] = QsH[ab + 4];   qaH[ks][3] = QsH[ab + 8 * KQ_STRIDE + 4];
        qaL[ks][0] = QsL[ab];       qaL[ks][1] = QsL[ab + 8 * KQ_STRIDE];
        qaL[ks][2] = QsL[ab + 4];   qaL[ks][3] = QsL[ab + 8 * KQ_STRIDE + 4];
    }

    const float pw = pair_w[h];
    float m0v = -1e30f, m1v = -1e30f;
    float lp0 = 0.f,   lp1 = 0.f;
    float Oacc[4][4];
#pragma unroll
    for (int i = 0; i < 4; i++)
#pragma unroll
        for (int j = 0; j < 4; j++) Oacc[i][j] = 0.f;

    const int row0 = q0 + wq + g;

    for (int kt = 0; kt < 4; kt++) {
        const int k0 = kt * 128;

        // ---- stage K tile (uint4 copy) ----
#pragma unroll
        for (int j = 0; j < 2; j++) {
            int id = j * 256 + tid;
            int r = id >> 2, w4 = (id & 3) * 4;
            uint4 vh = *reinterpret_cast<const uint4*>(kph + (bh * 512 + k0 + r) * 16 + w4);
            uint4 vl = *reinterpret_cast<const uint4*>(kpl + (bh * 512 + k0 + r) * 16 + w4);
            *reinterpret_cast<uint4*>(KsH + r * KQ_STRIDE + w4) = vh;
            *reinterpret_cast<uint4*>(KsL + r * KQ_STRIDE + w4) = vl;
        }
        // ---- stage V tile (uint4 copy; 32 d-rows x 64 pair-words) ----
#pragma unroll
        for (int j = 0; j < 2; j++) {
            int id = j * 256 + tid;
            int d = id >> 4, w4 = (id & 15) * 4;
            uint4 vh = *reinterpret_cast<const uint4*>(vph + (bh * 32 + d) * 256 + kt * 64 + w4);
            uint4 vl = *reinterpret_cast<const uint4*>(vpl + (bh * 32 + d) * 256 + kt * 64 + w4);
            *reinterpret_cast<uint4*>(VsH + d * V_STRIDE + w4) = vh;
            *reinterpret_cast<uint4*>(VsL + d * V_STRIDE + w4) = vl;
        }
        __syncthreads();

        float S[16][4];
#pragma unroll
        for (int nt = 0; nt < 16; nt++)
#pragma unroll
            for (int c = 0; c < 4; c++) S[nt][c] = 0.f;

#pragma unroll
        for (int ks = 0; ks < 2; ks++) {
#pragma unroll
            for (int nt = 0; nt < 16; nt++) {
                int bb = (nt * 8 + g) * KQ_STRIDE + ks * 8 + tg;
                unsigned bH0 = KsH[bb], bH1 = KsH[bb + 4];
                unsigned bL0 = KsL[bb], bL1 = KsL[bb + 4];
                mma_bf16v(S[nt], qaH[ks][0], qaH[ks][1], qaH[ks][2], qaH[ks][3], bH0, bH1);
                mma_bf16v(S[nt], qaH[ks][0], qaH[ks][1], qaH[ks][2], qaH[ks][3], bL0, bL1);
                mma_bf16v(S[nt], qaL[ks][0], qaL[ks][1], qaL[ks][2], qaL[ks][3], bH0, bH1);
            }
        }

#pragma unroll
        for (int nt = 0; nt < 16; nt++) {
            int col = k0 + nt * 8 + tg * 2;
            float2 bp0 = *reinterpret_cast<const float2*>(
                bppm + ((size_t)(b * LL + row0)) * LL + col);
            float2 bp1 = *reinterpret_cast<const float2*>(
                bppm + ((size_t)(b * LL + row0 + 8)) * LL + col);
            int i00 = row0 - col + 511;
            float mk0 = msk[col], mk1 = msk[col + 1];
            float s0 = S[nt][0] + bp0.x * pw + lut[i00];
            float s1 = S[nt][1] + bp0.y * pw + lut[i00 - 1];
            float s2 = S[nt][2] + bp1.x * pw + lut[i00 + 8];
            float s3 = S[nt][3] + bp1.y * pw + lut[i00 + 7];
            S[nt][0] = (mk0 != 0.f) ? s0 : -1e9f;
            S[nt][1] = (mk1 != 0.f) ? s1 : -1e9f;
            S[nt][2] = (mk0 != 0.f) ? s2 : -1e9f;
            S[nt][3] = (mk1 != 0.f) ? s3 : -1e9f;
        }

        float t0 = -1e30f, t1 = -1e30f;
#pragma unroll
        for (int nt = 0; nt < 16; nt++) {
            t0 = fmaxf(t0, fmaxf(S[nt][0], S[nt][1]));
            t1 = fmaxf(t1, fmaxf(S[nt][2], S[nt][3]));
        }
        t0 = fmaxf(t0, __shfl_xor_sync(0xffffffffu, t0, 1));
        t0 = fmaxf(t0, __shfl_xor_sync(0xffffffffu, t0, 2));
        t1 = fmaxf(t1, __shfl_xor_sync(0xffffffffu, t1, 1));
        t1 = fmaxf(t1, __shfl_xor_sync(0xffffffffu, t1, 2));

        float mn0 = fmaxf(m0v, t0), mn1 = fmaxf(m1v, t1);
        float al0 = __expf(m0v - mn0), al1 = __expf(m1v - mn1);
        m0v = mn0; m1v = mn1;

        float sum0 = 0.f, sum1 = 0.f;
#pragma unroll
        for (int nt = 0; nt < 16; nt++) {
            S[nt][0] = __expf(S[nt][0] - m0v);
            S[nt][1] = __expf(S[nt][1] - m0v);
            S[nt][2] = __expf(S[nt][2] - m1v);
            S[nt][3] = __expf(S[nt][3] - m1v);
            sum0 += S[nt][0] + S[nt][1];
            sum1 += S[nt][2] + S[nt][3];
        }
        lp0 = lp0 * al0 + sum0;
        lp1 = lp1 * al1 + sum1;
#pragma unroll
        for (int nt = 0; nt < 4; nt++) {
            Oacc[nt][0] *= al0; Oacc[nt][1] *= al0;
            Oacc[nt][2] *= al1; Oacc[nt][3] *= al1;
        }

#pragma unroll
        for (int j = 0; j < 8; j++) {
            unsigned pH0 = pack_bf16(S[2*j][0],   S[2*j][1]);
            unsigned pH1 = pack_bf16(S[2*j][2],   S[2*j][3]);
            unsigned pH2 = pack_bf16(S[2*j+1][0], S[2*j+1][1]);
            unsigned pH3 = pack_bf16(S[2*j+1][2], S[2*j+1][3]);
            unsigned pL0 = lo_residual(pH0, S[2*j][0],   S[2*j][1]);
            unsigned pL1 = lo_residual(pH1, S[2*j][2],   S[2*j][3]);
            unsigned pL2 = lo_residual(pH2, S[2*j+1][0], S[2*j+1][1]);
            unsigned pL3 = lo_residual(pH3, S[2*j+1][2], S[2*j+1][3]);
#pragma unroll
            for (int nt = 0; nt < 4; nt++) {
                int bb = (nt * 8 + g) * V_STRIDE + j * 8 + tg;
                unsigned bH0 = VsH[bb], bH1 = VsH[bb + 4];
                unsigned bL0 = VsL[bb], bL1 = VsL[bb + 4];
                mma_bf16v(Oacc[nt], pH0, pH1, pH2, pH3, bH0, bH1);
                mma_bf16v(Oacc[nt], pH0, pH1, pH2, pH3, bL0, bL1);
                mma_bf16v(Oacc[nt], pL0, pL1, pL2, pL3, bH0, bH1);
            }
        }
        __syncthreads();
    }

    float l0 = lp0 + __shfl_xor_sync(0xffffffffu, lp0, 1);
    l0 += __shfl_xor_sync(0xffffffffu, l0, 2);
    float l1 = lp1 + __shfl_xor_sync(0xffffffffu, lp1, 1);
    l1 += __shfl_xor_sync(0xffffffffu, l1, 2);
    float inv0 = 1.0f / l0, inv1 = 1.0f / l1;

    // ---- packed-fragment epilogue (GLOBAL row: b*LL + row0) ----
    int m16 = (b * LL + row0) >> 4;
#pragma unroll
    for (int nt = 0; nt < 4; nt++) {
        int kb = 2 * h + (nt >> 1);
        int cw = nt & 1;
        float f0 = Oacc[nt][0] * inv0, f1 = Oacc[nt][1] * inv0;
        float f2 = Oacc[nt][2] * inv1, f3 = Oacc[nt][3] * inv1;
        int base = ((m16 * 12 + kb) * 32 + g * 4 + tg) * 4 + 2 * cw;
        unsigned hw0 = pack_bf16(f0, f1);
        unsigned hw1 = pack_bf16(f2, f3);
        oHi[base]     = hw0;
        oLo[base]     = lo_residual(hw0, f0, f1);
        oHi[base + 1] = hw1;
        oLo[base + 1] = lo_residual(hw1, f2, f3);
    }
}

// ---------------- final projection ----------------
__global__ void proj_kernel(const float* __restrict__ x,
                            const float* __restrict__ pw,
                            const float* __restrict__ pb,
                            float* __restrict__ out) {
    int row  = blockIdx.x * 8 + (threadIdx.x >> 5);
    int lane = threadIdx.x & 31;
    const float* xr = x + (size_t)row * DDIM;
    float d0 = 0.f, d1 = 0.f;
#pragma unroll
    for (int j = 0; j < 6; j++) {
        int c = lane + 32*j;
        float v = xr[c];
        d0 += v * pw[c];
        d1 += v * pw[DDIM + c];
    }
#pragma unroll
    for (int o = 16; o; o >>= 1) {
        d0 += __shfl_xor_sync(0xffffffffu, d0, o);
        d1 += __shfl_xor_sync(0xffffffffu, d1, o);
    }
    if (lane == 0) {
        out[row*2 + 0] = d0 + pb[0];
        out[row*2 + 1] = d1 + pb[1];
    }
}

// ---------------- launch ----------------
extern "C" void kernel_launch(void* const* d_in, const int* in_sizes, int n_in,
                              void* d_out, int out_size) {
    const int*   seq      = (const int*)  d_in[0];
    const void*  mask     =               d_in[1];
    const float* bppm     = (const float*)d_in[2];
    const float* emb      = (const float*)d_in[3];
    const float* pair_w   = (const float*)d_in[4];
    const float* pair_b   = (const float*)d_in[5];
    const float* relpos_w = (const float*)d_in[6];
    const float* relpos_b = (const float*)d_in[7];
    const float* ln1_s    = (const float*)d_in[8];
    const float* ln1_b    = (const float*)d_in[9];
    const float* qkv_w    = (const float*)d_in[10];
    const float* qkv_b    = (const float*)d_in[11];
    const float* out_w    = (const float*)d_in[12];
    const float* out_b    = (const float*)d_in[13];
    const float* ln2_s    = (const float*)d_in[14];
    const float* ln2_b    = (const float*)d_in[15];
    const float* ff1_w    = (const float*)d_in[16];
    const float* ff1_b    = (const float*)d_in[17];
    const float* ff2_w    = (const float*)d_in[18];
    const float* ff2_b    = (const float*)d_in[19];
    const float* proj_w   = (const float*)d_in[20];
    const float* proj_b   = (const float*)d_in[21];
    float* out = (float*)d_out;

    float *x;
    unsigned *aAh, *aAl, *aBh, *aBl, *wh, *wl;
    unsigned *qph, *qpl, *kph, *kpl, *vph, *vpl;
    cudaGetSymbolAddress((void**)&x,    g_x);
    cudaGetSymbolAddress((void**)&aAh,  g_aA_hi);
    cudaGetSymbolAddress((void**)&aAl,  g_aA_lo);
    cudaGetSymbolAddress((void**)&aBh,  g_aB_hi);
    cudaGetSymbolAddress((void**)&aBl,  g_aB_lo);
    cudaGetSymbolAddress((void**)&wh,   g_w_hi);
    cudaGetSymbolAddress((void**)&wl,   g_w_lo);
    cudaGetSymbolAddress((void**)&qph,  g_qp_hi);
    cudaGetSymbolAddress((void**)&qpl,  g_qp_lo);
    cudaGetSymbolAddress((void**)&kph,  g_kp_hi);
    cudaGetSymbolAddress((void**)&kpl,  g_kp_lo);
    cudaGetSymbolAddress((void**)&vph,  g_vp_hi);
    cudaGetSymbolAddress((void**)&vpl,  g_vp_lo);

    static int attr_set = 0;
    if (!attr_set) {
        cudaFuncSetAttribute(attn_mma_kernel,
                             cudaFuncAttributeMaxDynamicSharedMemorySize, SMEM_ATT_BYTES);
        attr_set = 1;
    }

    auto WHI = [&](int layer, int off4) { return wh + ((size_t)layer * WPK_L4 + off4) * 4; };
    auto WLO = [&](int layer, int off4) { return wl + ((size_t)layer * WPK_L4 + off4) * 4; };

    dim3 gQKV(QKVN / 64, NROW / 128);   // 9 x 128
    dim3 gOUT(DDIM / 64, NROW / 128);   // 3 x 128
    dim3 gFF1(FFN  / 64, NROW / 128);   // 12 x 128
    dim3 gATT(LL / 128, HH, BB);        // 4 x 6 x 32

    // ---- launch order keeps QKV gemm at slot 3 ----
    embed_kernel<<<(NROW * DDIM) / 256, 256>>>(seq, emb, x);                       // 0
    ln_pack_kernel<<<NROW / 8, 256>>>(x, ln1_s, ln1_b, aAh, aAl);                  // 1
    pack_w_kernel<<<(DEPTH*18*12 + 7) / 8, 256>>>(qkv_w, wh, wl, QKVN, DDIM, OFF_QKV4);  // 2
    gemm_pk_kernel<3><<<gQKV, 256>>>(aAh, aAl, WHI(0, OFF_QKV4), WLO(0, OFF_QKV4), // 3 (profiled)
                                     qkv_b, nullptr, nullptr,
                                     qph, qpl, kph, kpl, vph, vpl,
                                     NROW, QKVN, DDIM, 0);
    pack_w_kernel<<<(DEPTH*6*12  + 7) / 8, 256>>>(out_w, wh, wl, DDIM, DDIM, OFF_OUT4);
    pack_w_kernel<<<(DEPTH*24*12 + 7) / 8, 256>>>(ff1_w, wh, wl, FFN, DDIM, OFF_FF14);
    pack_w_kernel<<<(DEPTH*6*48  + 7) / 8, 256>>>(ff2_w, wh, wl, DDIM, FFN, OFF_FF24);
    mask_reset_kernel<<<1, 1>>>();
    mask_detect_kernel<<<(NROW + 255) / 256, 256>>>((const unsigned char*)mask);
    mask_expand_kernel<<<(NROW + 255) / 256, 256>>>(mask);

    for (int i = 0; i < DEPTH; i++) {
        attn_mma_kernel<<<gATT, 256, SMEM_ATT_BYTES>>>(qph, qpl, kph, kpl, vph, vpl,
                                                       bppm, pair_w, pair_b,
                                                       relpos_w, relpos_b, aAh, aAl);
        gemm_pk_kernel<1><<<gOUT, 256>>>(aAh, aAl, WHI(i, OFF_OUT4), WLO(i, OFF_OUT4),
                                         out_b + i*DDIM, x, x,
                                         nullptr, nullptr, nullptr, nullptr, nullptr, nullptr,
                                         NROW, DDIM, DDIM, 0);
        ln_pack_kernel<<<NROW / 8, 256>>>(x, ln2_s + i*DDIM, ln2_b + i*DDIM, aAh, aAl);
        gemm_pk_kernel<2><<<gFF1, 256>>>(aAh, aAl, WHI(i, OFF_FF14), WLO(i, OFF_FF14),
                                         ff1_b + i*FFN, nullptr, nullptr,
                                         aBh, aBl, nullptr, nullptr, nullptr, nullptr,
                                         NROW, FFN, DDIM, 48);
        gemm_pk_kernel<1><<<gOUT, 256>>>(aBh, aBl, WHI(i, OFF_FF24), WLO(i, OFF_FF24),
                                         ff2_b + i*DDIM, x, x,
                                         nullptr, nullptr, nullptr, nullptr, nullptr, nullptr,
                                         NROW, DDIM, FFN, 0);
        if (i + 1 < DEPTH) {
            ln_pack_kernel<<<NROW / 8, 256>>>(x, ln1_s + (i+1)*DDIM, ln1_b + (i+1)*DDIM,
                                              aAh, aAl);
            gemm_pk_kernel<3><<<gQKV, 256>>>(aAh, aAl,
                                             WHI(i+1, OFF_QKV4), WLO(i+1, OFF_QKV4),
                                             qkv_b + (i+1)*QKVN, nullptr, nullptr,
                                             qph, qpl, kph, kpl, vph, vpl,
                                             NROW, QKVN, DDIM, 0);
        }
    }

    proj_kernel<<<NROW / 8, 256>>>(x, proj_w, proj_b, out);
}

// round 16
// speedup vs baseline: 1.0475x; 1.0475x over previous
#include <cuda_runtime.h>
#include <cuda_bf16.h>
#include <math.h>
#include <stdint.h>

// ---------------- problem constants ----------------
#define BB   32
#define LL   512
#define DDIM 192
#define DEPTH 12
#define HH   6
#define DHH  32
#define KCLIP 32
#define BINS 65
#define NROW (BB*LL)          // 16384
#define QKVN (3*DDIM)         // 576
#define FFN  (4*DDIM)         // 768
#define SCALE_Q 0.17677669529663687f

// ---------------- scratch ----------------
__device__ float g_x  [NROW*DDIM];
__device__ float g_qkv[NROW*QKVN];
__device__ float g_maskf[NROW];
__device__ int   g_mask_is_u8;

// packed activation fragments (bf16 hi/lo words, mma-fragment layout)
#define APK_A_WORDS (NROW*DDIM/2)    // K=192 layout (NKB=12)
#define APK_B_WORDS (NROW*FFN/2)     // K=768 layout (NKB=48)
__device__ unsigned g_aA_hi[APK_A_WORDS], g_aA_lo[APK_A_WORDS];
__device__ unsigned g_aB_hi[APK_B_WORDS], g_aB_lo[APK_B_WORDS];

// packed weight fragments, all layers
#define WPK_L4 55296                 // uint4 per layer (qkv+out+ff1+ff2)
#define OFF_QKV4 0
#define OFF_OUT4 13824
#define OFF_FF14 18432
#define OFF_FF24 36864
__device__ unsigned g_w_hi[WPK_L4*DEPTH*4], g_w_lo[WPK_L4*DEPTH*4];

// ---------------- mask handling ----------------
__global__ void mask_reset_kernel() { g_mask_is_u8 = 0; }
__global__ void mask_detect_kernel(const unsigned char* __restrict__ m) {
    int i = blockIdx.x * 256 + threadIdx.x;
    if (i < NROW && (i & 3) != 0 && m[i] != 0) atomicOr(&g_mask_is_u8, 1);
}
__global__ void mask_expand_kernel(const void* __restrict__ m) {
    int i = blockIdx.x * 256 + threadIdx.x;
    if (i >= NROW) return;
    int v;
    if (g_mask_is_u8) v = ((const unsigned char*)m)[i];
    else              v = ((const int*)m)[i];
    g_maskf[i] = v ? 1.0f : 0.0f;
}

// ---------------- embedding ----------------
__global__ void embed_kernel(const int* __restrict__ seq,
                             const float* __restrict__ emb,
                             float* __restrict__ x) {
    int i = blockIdx.x * 256 + threadIdx.x;
    if (i >= NROW * DDIM) return;
    int row = i / DDIM, c = i - row * DDIM;
    x[i] = emb[seq[row] * DDIM + c];
}

// ---------------- bf16 helpers ----------------
__device__ __forceinline__ unsigned pack_bf16(float lo, float hi) {
    unsigned r;
    asm("cvt.rn.bf16x2.f32 %0, %1, %2;" : "=r"(r) : "f"(hi), "f"(lo));
    return r;
}
__device__ __forceinline__ unsigned lo_residual(unsigned hiw, float lo, float hi) {
    float h0 = __uint_as_float(hiw << 16);
    float h1 = __uint_as_float(hiw & 0xffff0000u);
    return pack_bf16(lo - h0, hi - h1);
}
__device__ __forceinline__ void mma_bf16v(float* c,
                                          unsigned a0, unsigned a1, unsigned a2, unsigned a3,
                                          unsigned b0, unsigned b1) {
    asm("mma.sync.aligned.m16n8k16.row.col.f32.bf16.bf16.f32 "
        "{%0,%1,%2,%3},{%4,%5,%6,%7},{%8,%9},{%0,%1,%2,%3};"
        : "+f"(c[0]), "+f"(c[1]), "+f"(c[2]), "+f"(c[3])
        : "r"(a0), "r"(a1), "r"(a2), "r"(a3), "r"(b0), "r"(b1));
}

// ---------------- layernorm + fragment pack (warp per row) ----------------
__global__ void ln_pack_kernel(const float* __restrict__ x,
                               const float* __restrict__ s, const float* __restrict__ bb,
                               unsigned* __restrict__ hi, unsigned* __restrict__ lo) {
    int row  = blockIdx.x * 8 + (threadIdx.x >> 5);
    int lane = threadIdx.x & 31;
    const float* xr = x + (size_t)row * DDIM;
    float2 v[3]; float sum = 0.f;
#pragma unroll
    for (int jj = 0; jj < 3; jj++) {
        v[jj] = *reinterpret_cast<const float2*>(xr + 2 * (lane + 32 * jj));
        sum += v[jj].x + v[jj].y;
    }
#pragma unroll
    for (int o = 16; o; o >>= 1) sum += __shfl_xor_sync(0xffffffffu, sum, o);
    float mu = sum * (1.0f / DDIM);
    float vs = 0.f;
#pragma unroll
    for (int jj = 0; jj < 3; jj++) {
        float d0 = v[jj].x - mu, d1 = v[jj].y - mu;
        vs += d0 * d0 + d1 * d1;
    }
#pragma unroll
    for (int o = 16; o; o >>= 1) vs += __shfl_xor_sync(0xffffffffu, vs, o);
    float inv = rsqrtf(vs * (1.0f / DDIM) + 1e-5f);

    int m16 = row >> 4, g8 = row & 7, hi8 = (row >> 3) & 1;
#pragma unroll
    for (int jj = 0; jj < 3; jj++) {
        int p = lane + 32 * jj;
        int kb = p >> 3, tgp = p & 3, cw = (p >> 2) & 1;
        float2 sv = *reinterpret_cast<const float2*>(s + 2 * p);
        float2 bv = *reinterpret_cast<const float2*>(bb + 2 * p);
        float f0 = (v[jj].x - mu) * inv * sv.x + bv.x;
        float f1 = (v[jj].y - mu) * inv * sv.y + bv.y;
        unsigned hw = pack_bf16(f0, f1);
        int idx = ((m16 * 12 + kb) * 32 + g8 * 4 + tgp) * 4 + hi8 + 2 * cw;
        hi[idx] = hw;
        lo[idx] = lo_residual(hw, f0, f1);
    }
}

// ---------------- weight fragment pack (warp per (layer, n32, kb)) ----------------
__global__ void pack_w_kernel(const float* __restrict__ W, unsigned* __restrict__ hiW,
                              unsigned* __restrict__ loW, int N, int K, int dstBase4) {
    int wid  = blockIdx.x * 8 + (threadIdx.x >> 5);
    int lane = threadIdx.x & 31, g = lane >> 2, tg = lane & 3;
    int NKB = K >> 4, perL = (N >> 5) * NKB;
    if (wid >= DEPTH * perL) return;
    int l = wid / perL, rem = wid - l * perL;
    int n32 = rem / NKB, kb = rem - n32 * NKB;
    const float* Wl = W + (size_t)l * N * K;
    unsigned wh[8], wl[8];
#pragma unroll
    for (int j = 0; j < 4; j++) {
        int n = n32 * 32 + j * 8 + g;
        const float* p = Wl + (size_t)n * K + kb * 16;
        float2 u = *reinterpret_cast<const float2*>(p + 2 * tg);
        float2 q = *reinterpret_cast<const float2*>(p + 8 + 2 * tg);
        wh[j*2]   = pack_bf16(u.x, u.y);
        wl[j*2]   = lo_residual(wh[j*2], u.x, u.y);
        wh[j*2+1] = pack_bf16(q.x, q.y);
        wl[j*2+1] = lo_residual(wh[j*2+1], q.x, q.y);
    }
    size_t o4 = (size_t)l * WPK_L4 + dstBase4 + (size_t)(n32 * NKB + kb) * 64 + lane;
    uint4* H = reinterpret_cast<uint4*>(hiW);
    uint4* L = reinterpret_cast<uint4*>(loW);
    H[o4]      = make_uint4(wh[0], wh[1], wh[2], wh[3]);
    H[o4 + 32] = make_uint4(wh[4], wh[5], wh[6], wh[7]);
    L[o4]      = make_uint4(wl[0], wl[1], wl[2], wl[3]);
    L[o4 + 32] = make_uint4(wl[4], wl[5], wl[6], wl[7]);
}

// ================= fragment-direct GEMM (no smem, no syncs) =================
// C[M,N] = A@W^T; A/B pre-packed fragments; 3-pass hi/lo; BM=128 BN=64; 8 warps 4x2.
// MODE 0: C=acc+bias (fp32)  1: C=acc+bias+res (fp32)  2: gelu(acc+bias) -> packed out
template <int MODE>
__global__ __launch_bounds__(256, 2)
void gemm_pk_kernel(const unsigned* __restrict__ AhiW, const unsigned* __restrict__ AloW,
                    const unsigned* __restrict__ BhiW, const unsigned* __restrict__ BloW,
                    const float* __restrict__ bias, const float* __restrict__ res,
                    float* __restrict__ C, unsigned* __restrict__ Phi, unsigned* __restrict__ Plo,
                    int M, int N, int K, int NKB_OUT) {
    const uint4* Ahi = reinterpret_cast<const uint4*>(AhiW);
    const uint4* Alo = reinterpret_cast<const uint4*>(AloW);
    const uint4* Bhi = reinterpret_cast<const uint4*>(BhiW);
    const uint4* Blo = reinterpret_cast<const uint4*>(BloW);

    const int tid = threadIdx.x, lane = tid & 31, wid = tid >> 5;
    const int g = lane >> 2, tg = lane & 3;
    const int wm = (wid & 3) * 32, wn = (wid >> 2) * 32;
    const int m0 = blockIdx.y * 128, n0 = blockIdx.x * 64;
    const int NKB = K >> 4;
    const size_t m16a = (size_t)((m0 + wm) >> 4);
    const size_t n32  = (size_t)((n0 + wn) >> 5);

    const uint4* pa0h = Ahi + m16a * NKB * 32 + lane;
    const uint4* pa1h = Ahi + (m16a + 1) * NKB * 32 + lane;
    const uint4* pa0l = Alo + m16a * NKB * 32 + lane;
    const uint4* pa1l = Alo + (m16a + 1) * NKB * 32 + lane;
    const uint4* pbh  = Bhi + n32 * NKB * 64 + lane;
    const uint4* pbl  = Blo + n32 * NKB * 64 + lane;

    float acc[2][4][4];
#pragma unroll
    for (int i = 0; i < 2; i++)
#pragma unroll
        for (int j = 0; j < 4; j++)
#pragma unroll
            for (int t = 0; t < 4; t++) acc[i][j][t] = 0.f;

    uint4 cA0h = pa0h[0], cA1h = pa1h[0], cA0l = pa0l[0], cA1l = pa1l[0];
    uint4 cB0h = pbh[0], cB1h = pbh[32], cB0l = pbl[0], cB1l = pbl[32];

    for (int kb = 0; kb < NKB; kb++) {
        uint4 nA0h, nA1h, nA0l, nA1l, nB0h, nB1h, nB0l, nB1l;
        if (kb + 1 < NKB) {
            int off = (kb + 1) * 32, offb = (kb + 1) * 64;
            nA0h = pa0h[off]; nA1h = pa1h[off];
            nA0l = pa0l[off]; nA1l = pa1l[off];
            nB0h = pbh[offb]; nB1h = pbh[offb + 32];
            nB0l = pbl[offb]; nB1l = pbl[offb + 32];
        }
        unsigned aH[2][4] = {{cA0h.x, cA0h.y, cA0h.z, cA0h.w},
                             {cA1h.x, cA1h.y, cA1h.z, cA1h.w}};
        unsigned aL[2][4] = {{cA0l.x, cA0l.y, cA0l.z, cA0l.w},
                             {cA1l.x, cA1l.y, cA1l.z, cA1l.w}};
        unsigned bH[2][4] = {{cB0h.x, cB0h.y, cB0h.z, cB0h.w},
                             {cB1h.x, cB1h.y, cB1h.z, cB1h.w}};
        unsigned bL[2][4] = {{cB0l.x, cB0l.y, cB0l.z, cB0l.w},
                             {cB1l.x, cB1l.y, cB1l.z, cB1l.w}};
#pragma unroll
        for (int mf = 0; mf < 2; mf++) {
#pragma unroll
            for (int nf = 0; nf < 4; nf++) {
                unsigned b0 = bH[nf >> 1][(nf & 1) * 2];
                unsigned b1 = bH[nf >> 1][(nf & 1) * 2 + 1];
                unsigned l0 = bL[nf >> 1][(nf & 1) * 2];
                unsigned l1 = bL[nf >> 1][(nf & 1) * 2 + 1];
                mma_bf16v(acc[mf][nf], aH[mf][0], aH[mf][1], aH[mf][2], aH[mf][3], b0, b1);
                mma_bf16v(acc[mf][nf], aH[mf][0], aH[mf][1], aH[mf][2], aH[mf][3], l0, l1);
                mma_bf16v(acc[mf][nf], aL[mf][0], aL[mf][1], aL[mf][2], aL[mf][3], b0, b1);
            }
        }
        cA0h = nA0h; cA1h = nA1h; cA0l = nA0l; cA1l = nA1l;
        cB0h = nB0h; cB1h = nB1h; cB0l = nB0l; cB1l = nB1l;
    }

    if (MODE == 2) {
        // packed output: ff fragments for FF2 (K=768 layout)
#pragma unroll
        for (int mf = 0; mf < 2; mf++) {
            int m16o = ((m0 + wm) >> 4) + mf;
#pragma unroll
            for (int nf = 0; nf < 4; nf++) {
                int c = n0 + wn + nf * 8 + tg * 2;
                float2 bi = *reinterpret_cast<const float2*>(bias + c);
                int kb2 = (n0 >> 4) + (wn >> 4) + (nf >> 1);
                int cw  = nf & 1;
#pragma unroll
                for (int half = 0; half < 2; half++) {
                    float v0 = acc[mf][nf][half * 2 + 0] + bi.x;
                    float v1 = acc[mf][nf][half * 2 + 1] + bi.y;
                    v0 = 0.5f * v0 * (1.0f + erff(v0 * 0.7071067811865476f));
                    v1 = 0.5f * v1 * (1.0f + erff(v1 * 0.7071067811865476f));
                    unsigned hw = pack_bf16(v0, v1);
                    int idx = ((m16o * NKB_OUT + kb2) * 32 + g * 4 + tg) * 4 + half + 2 * cw;
                    Phi[idx] = hw;
                    Plo[idx] = lo_residual(hw, v0, v1);
                }
            }
        }
    } else {
#pragma unroll
        for (int mf = 0; mf < 2; mf++) {
            int r = m0 + wm + mf * 16 + g;
#pragma unroll
            for (int nf = 0; nf < 4; nf++) {
                int c = n0 + wn + nf * 8 + tg * 2;
                float2 bi = *reinterpret_cast<const float2*>(bias + c);
#pragma unroll
                for (int half = 0; half < 2; half++) {
                    int rr = r + half * 8;
                    float v0 = acc[mf][nf][half * 2 + 0] + bi.x;
                    float v1 = acc[mf][nf][half * 2 + 1] + bi.y;
                    if (MODE == 1) {
                        float2 rv = *reinterpret_cast<const float2*>(res + (size_t)rr * N + c);
                        v0 += rv.x; v1 += rv.y;
                    }
                    *reinterpret_cast<float2*>(C + (size_t)rr * N + c) = make_float2(v0, v1);
                }
            }
        }
    }
}

// ================= flash attention: 2-pass split (Qhi·K, Phi·V) =================
#define KQ_STRIDE 20
#define V_STRIDE  69
#define OFF_KH 0
#define OFF_KL 2560
#define OFF_QH 5120
#define OFF_VH 7680
#define OFF_VL 9888
#define OFF_LUT 12096
#define OFF_MSK (12096+1023)
#define SMEM_ATT_WORDS (12096+1023+512+9)
#define SMEM_ATT_BYTES (SMEM_ATT_WORDS*4)

__global__ __launch_bounds__(256, 2)
void attn_mma_kernel(const float* __restrict__ qkv, const float* __restrict__ bppm,
                     const float* __restrict__ pair_w, const float* __restrict__ pair_b,
                     const float* __restrict__ relpos_w, const float* __restrict__ relpos_b,
                     unsigned* __restrict__ oHi, unsigned* __restrict__ oLo) {
    extern __shared__ unsigned sm[];
    unsigned* KsH = sm + OFF_KH;
    unsigned* KsL = sm + OFF_KL;
    unsigned* QsH = sm + OFF_QH;
    unsigned* VsH = sm + OFF_VH;
    unsigned* VsL = sm + OFF_VL;
    float*    lut = (float*)(sm + OFF_LUT);
    float*    msk = (float*)(sm + OFF_MSK);

    const int tid  = threadIdx.x;
    const int lane = tid & 31;
    const int w    = tid >> 5;
    const int qt   = blockIdx.x;
    const int h    = blockIdx.y;
    const int b    = blockIdx.z;
    const int q0   = qt * 128;
    const int wq   = w * 16;
    const int g    = lane >> 2;
    const int tg   = lane & 3;

    // ---- stage Q (scale folded; hi only — 2-pass) ----
#pragma unroll
    for (int j = 0; j < 4; j++) {
        int r  = w * 16 + j * 4 + (lane >> 3);
        int c4 = (lane & 7) * 4;
        float4 v = *reinterpret_cast<const float4*>(
            qkv + (size_t)(b * LL + q0 + r) * QKVN + h * DHH + c4);
        v.x *= SCALE_Q; v.y *= SCALE_Q; v.z *= SCALE_Q; v.w *= SCALE_Q;
        int base = r * KQ_STRIDE + (c4 >> 1);
        QsH[base]     = pack_bf16(v.x, v.y);
        QsH[base + 1] = pack_bf16(v.z, v.w);
    }
    const float addc = pair_b[h] + relpos_b[h];
#pragma unroll
    for (int j = 0; j < 4; j++) {
        int i = j * 256 + tid;
        if (i < 1023) {
            int d = i - 511;
            int cd = min(KCLIP, max(-KCLIP, d)) + KCLIP;
            lut[i] = relpos_w[h * BINS + cd] + addc;
        }
    }
    for (int k = tid; k < LL; k += 256) msk[k] = g_maskf[b * LL + k];
    __syncthreads();

    // ---- hoist Q fragments (hi only) ----
    unsigned qaH[2][4];
#pragma unroll
    for (int ks = 0; ks < 2; ks++) {
        int ab = (wq + g) * KQ_STRIDE + ks * 8 + tg;
        qaH[ks][0] = QsH[ab];       qaH[ks][1] = QsH[ab + 8 * KQ_STRIDE];
        qaH[ks][2] = QsH[ab + 4];   qaH[ks][3] = QsH[ab + 8 * KQ_STRIDE + 4];
    }

    const float pw = pair_w[h];
    float m0v = -1e30f, m1v = -1e30f;
    float lp0 = 0.f,   lp1 = 0.f;
    float Oacc[4][4];
#pragma unroll
    for (int i = 0; i < 4; i++)
#pragma unroll
        for (int j = 0; j < 4; j++) Oacc[i][j] = 0.f;

    const int row0 = q0 + wq + g;

    for (int kt = 0; kt < 4; kt++) {
        const int k0 = kt * 128;

        // ---- stage K tile (hi + lo) ----
#pragma unroll
        for (int j = 0; j < 4; j++) {
            int r  = w * 16 + j * 4 + (lane >> 3);
            int c4 = (lane & 7) * 4;
            float4 v = *reinterpret_cast<const float4*>(
                qkv + (size_t)(b * LL + k0 + r) * QKVN + DDIM + h * DHH + c4);
            unsigned h0 = pack_bf16(v.x, v.y);
            unsigned h1 = pack_bf16(v.z, v.w);
            int base = r * KQ_STRIDE + (c4 >> 1);
            KsH[base]     = h0;
            KsH[base + 1] = h1;
            KsL[base]     = lo_residual(h0, v.x, v.y);
            KsL[base + 1] = lo_residual(h1, v.z, v.w);
        }
        // ---- stage V tile transposed (hi + lo) ----
#pragma unroll
        for (int j = 0; j < 2; j++) {
            int p  = w * 8 + j * 4 + (lane >> 3);
            int d4 = (lane & 7) * 4;
            const float* base = qkv + (size_t)(b * LL + k0 + 2 * p) * QKVN + 2 * DDIM + h * DHH + d4;
            float4 v0 = *reinterpret_cast<const float4*>(base);
            float4 v1 = *reinterpret_cast<const float4*>(base + QKVN);
            float a0[4] = {v0.x, v0.y, v0.z, v0.w};
            float a1[4] = {v1.x, v1.y, v1.z, v1.w};
#pragma unroll
            for (int i = 0; i < 4; i++) {
                unsigned hw = pack_bf16(a0[i], a1[i]);
                VsH[(d4 + i) * V_STRIDE + p] = hw;
                VsL[(d4 + i) * V_STRIDE + p] = lo_residual(hw, a0[i], a1[i]);
            }
        }
        __syncthreads();

        // ---- S = Qhi·(Khi + Klo) : 2 passes ----
        float S[16][4];
#pragma unroll
        for (int nt = 0; nt < 16; nt++)
#pragma unroll
            for (int c = 0; c < 4; c++) S[nt][c] = 0.f;

#pragma unroll
        for (int ks = 0; ks < 2; ks++) {
#pragma unroll
            for (int nt = 0; nt < 16; nt++) {
                int bb = (nt * 8 + g) * KQ_STRIDE + ks * 8 + tg;
                unsigned bH0 = KsH[bb], bH1 = KsH[bb + 4];
                unsigned bL0 = KsL[bb], bL1 = KsL[bb + 4];
                mma_bf16v(S[nt], qaH[ks][0], qaH[ks][1], qaH[ks][2], qaH[ks][3], bH0, bH1);
                mma_bf16v(S[nt], qaH[ks][0], qaH[ks][1], qaH[ks][2], qaH[ks][3], bL0, bL1);
            }
        }

#pragma unroll
        for (int nt = 0; nt < 16; nt++) {
            int col = k0 + nt * 8 + tg * 2;
            float2 bp0 = *reinterpret_cast<const float2*>(
                bppm + ((size_t)(b * LL + row0)) * LL + col);
            float2 bp1 = *reinterpret_cast<const float2*>(
                bppm + ((size_t)(b * LL + row0 + 8)) * LL + col);
            int i00 = row0 - col + 511;
            float mk0 = msk[col], mk1 = msk[col + 1];
            float s0 = S[nt][0] + bp0.x * pw + lut[i00];
            float s1 = S[nt][1] + bp0.y * pw + lut[i00 - 1];
            float s2 = S[nt][2] + bp1.x * pw + lut[i00 + 8];
            float s3 = S[nt][3] + bp1.y * pw + lut[i00 + 7];
            S[nt][0] = (mk0 != 0.f) ? s0 : -1e9f;
            S[nt][1] = (mk1 != 0.f) ? s1 : -1e9f;
            S[nt][2] = (mk0 != 0.f) ? s2 : -1e9f;
            S[nt][3] = (mk1 != 0.f) ? s3 : -1e9f;
        }

        float t0 = -1e30f, t1 = -1e30f;
#pragma unroll
        for (int nt = 0; nt < 16; nt++) {
            t0 = fmaxf(t0, fmaxf(S[nt][0], S[nt][1]));
            t1 = fmaxf(t1, fmaxf(S[nt][2], S[nt][3]));
        }
        t0 = fmaxf(t0, __shfl_xor_sync(0xffffffffu, t0, 1));
        t0 = fmaxf(t0, __shfl_xor_sync(0xffffffffu, t0, 2));
        t1 = fmaxf(t1, __shfl_xor_sync(0xffffffffu, t1, 1));
        t1 = fmaxf(t1, __shfl_xor_sync(0xffffffffu, t1, 2));

        float mn0 = fmaxf(m0v, t0), mn1 = fmaxf(m1v, t1);
        float al0 = __expf(m0v - mn0), al1 = __expf(m1v - mn1);
        m0v = mn0; m1v = mn1;

        float sum0 = 0.f, sum1 = 0.f;
#pragma unroll
        for (int nt = 0; nt < 16; nt++) {
            S[nt][0] = __expf(S[nt][0] - m0v);
            S[nt][1] = __expf(S[nt][1] - m0v);
            S[nt][2] = __expf(S[nt][2] - m1v);
            S[nt][3] = __expf(S[nt][3] - m1v);
            sum0 += S[nt][0] + S[nt][1];
            sum1 += S[nt][2] + S[nt][3];
        }
        lp0 = lp0 * al0 + sum0;
        lp1 = lp1 * al1 + sum1;
#pragma unroll
        for (int nt = 0; nt < 4; nt++) {
            Oacc[nt][0] *= al0; Oacc[nt][1] *= al0;
            Oacc[nt][2] *= al1; Oacc[nt][3] *= al1;
        }

        // ---- O += Phi·(Vhi + Vlo) : 2 passes ----
#pragma unroll
        for (int j = 0; j < 8; j++) {
            unsigned pH0 = pack_bf16(S[2*j][0],   S[2*j][1]);
            unsigned pH1 = pack_bf16(S[2*j][2],   S[2*j][3]);
            unsigned pH2 = pack_bf16(S[2*j+1][0], S[2*j+1][1]);
            unsigned pH3 = pack_bf16(S[2*j+1][2], S[2*j+1][3]);
#pragma unroll
            for (int nt = 0; nt < 4; nt++) {
                int bb = (nt * 8 + g) * V_STRIDE + j * 8 + tg;
                unsigned bH0 = VsH[bb], bH1 = VsH[bb + 4];
                unsigned bL0 = VsL[bb], bL1 = VsL[bb + 4];
                mma_bf16v(Oacc[nt], pH0, pH1, pH2, pH3, bH0, bH1);
                mma_bf16v(Oacc[nt], pH0, pH1, pH2, pH3, bL0, bL1);
            }
        }
        __syncthreads();
    }

    float l0 = lp0 + __shfl_xor_sync(0xffffffffu, lp0, 1);
    l0 += __shfl_xor_sync(0xffffffffu, l0, 2);
    float l1 = lp1 + __shfl_xor_sync(0xffffffffu, lp1, 1);
    l1 += __shfl_xor_sync(0xffffffffu, l1, 2);
    float inv0 = 1.0f / l0, inv1 = 1.0f / l1;

    // ---- packed-fragment epilogue (GLOBAL row: b*LL + row0) ----
    int m16 = (b * LL + row0) >> 4;
#pragma unroll
    for (int nt = 0; nt < 4; nt++) {
        int kb = 2 * h + (nt >> 1);
        int cw = nt & 1;
        float f0 = Oacc[nt][0] * inv0, f1 = Oacc[nt][1] * inv0;
        float f2 = Oacc[nt][2] * inv1, f3 = Oacc[nt][3] * inv1;
        int base = ((m16 * 12 + kb) * 32 + g * 4 + tg) * 4 + 2 * cw;
        unsigned hw0 = pack_bf16(f0, f1);
        unsigned hw1 = pack_bf16(f2, f3);
        oHi[base]     = hw0;
        oLo[base]     = lo_residual(hw0, f0, f1);
        oHi[base + 1] = hw1;
        oLo[base + 1] = lo_residual(hw1, f2, f3);
    }
}

// ---------------- final projection ----------------
__global__ void proj_kernel(const float* __restrict__ x,
                            const float* __restrict__ pw,
                            const float* __restrict__ pb,
                            float* __restrict__ out) {
    int row  = blockIdx.x * 8 + (threadIdx.x >> 5);
    int lane = threadIdx.x & 31;
    const float* xr = x + (size_t)row * DDIM;
    float d0 = 0.f, d1 = 0.f;
#pragma unroll
    for (int j = 0; j < 6; j++) {
        int c = lane + 32*j;
        float v = xr[c];
        d0 += v * pw[c];
        d1 += v * pw[DDIM + c];
    }
#pragma unroll
    for (int o = 16; o; o >>= 1) {
        d0 += __shfl_xor_sync(0xffffffffu, d0, o);
        d1 += __shfl_xor_sync(0xffffffffu, d1, o);
    }
    if (lane == 0) {
        out[row*2 + 0] = d0 + pb[0];
        out[row*2 + 1] = d1 + pb[1];
    }
}

// ---------------- launch ----------------
extern "C" void kernel_launch(void* const* d_in, const int* in_sizes, int n_in,
                              void* d_out, int out_size) {
    const int*   seq      = (const int*)  d_in[0];
    const void*  mask     =               d_in[1];
    const float* bppm     = (const float*)d_in[2];
    const float* emb      = (const float*)d_in[3];
    const float* pair_w   = (const float*)d_in[4];
    const float* pair_b   = (const float*)d_in[5];
    const float* relpos_w = (const float*)d_in[6];
    const float* relpos_b = (const float*)d_in[7];
    const float* ln1_s    = (const float*)d_in[8];
    const float* ln1_b    = (const float*)d_in[9];
    const float* qkv_w    = (const float*)d_in[10];
    const float* qkv_b    = (const float*)d_in[11];
    const float* out_w    = (const float*)d_in[12];
    const float* out_b    = (const float*)d_in[13];
    const float* ln2_s    = (const float*)d_in[14];
    const float* ln2_b    = (const float*)d_in[15];
    const float* ff1_w    = (const float*)d_in[16];
    const float* ff1_b    = (const float*)d_in[17];
    const float* ff2_w    = (const float*)d_in[18];
    const float* ff2_b    = (const float*)d_in[19];
    const float* proj_w   = (const float*)d_in[20];
    const float* proj_b   = (const float*)d_in[21];
    float* out = (float*)d_out;

    float *x, *qkvB;
    unsigned *aAh, *aAl, *aBh, *aBl, *wh, *wl;
    cudaGetSymbolAddress((void**)&x,    g_x);
    cudaGetSymbolAddress((void**)&qkvB, g_qkv);
    cudaGetSymbolAddress((void**)&aAh,  g_aA_hi);
    cudaGetSymbolAddress((void**)&aAl,  g_aA_lo);
    cudaGetSymbolAddress((void**)&aBh,  g_aB_hi);
    cudaGetSymbolAddress((void**)&aBl,  g_aB_lo);
    cudaGetSymbolAddress((void**)&wh,   g_w_hi);
    cudaGetSymbolAddress((void**)&wl,   g_w_lo);

    static int attr_set = 0;
    if (!attr_set) {
        cudaFuncSetAttribute(attn_mma_kernel,
                             cudaFuncAttributeMaxDynamicSharedMemorySize, SMEM_ATT_BYTES);
        attr_set = 1;
    }

    auto WHI = [&](int layer, int off4) { return wh + ((size_t)layer * WPK_L4 + off4) * 4; };
    auto WLO = [&](int layer, int off4) { return wl + ((size_t)layer * WPK_L4 + off4) * 4; };

    dim3 gQKV(QKVN / 64, NROW / 128);   // 9 x 128
    dim3 gOUT(DDIM / 64, NROW / 128);   // 3 x 128
    dim3 gFF1(FFN  / 64, NROW / 128);   // 12 x 128
    dim3 gATT(LL / 128, HH, BB);        // 4 x 6 x 32

    // ---- launch order keeps gemm<0> at slot 3 ----
    embed_kernel<<<(NROW * DDIM) / 256, 256>>>(seq, emb, x);                       // 0
    ln_pack_kernel<<<NROW / 8, 256>>>(x, ln1_s, ln1_b, aAh, aAl);                  // 1
    pack_w_kernel<<<(DEPTH*18*12 + 7) / 8, 256>>>(qkv_w, wh, wl, QKVN, DDIM, OFF_QKV4);  // 2
    gemm_pk_kernel<0><<<gQKV, 256>>>(aAh, aAl, WHI(0, OFF_QKV4), WLO(0, OFF_QKV4), // 3 (profiled)
                                     qkv_b, nullptr, qkvB, nullptr, nullptr,
                                     NROW, QKVN, DDIM, 0);
    pack_w_kernel<<<(DEPTH*6*12  + 7) / 8, 256>>>(out_w, wh, wl, DDIM, DDIM, OFF_OUT4);
    pack_w_kernel<<<(DEPTH*24*12 + 7) / 8, 256>>>(ff1_w, wh, wl, FFN, DDIM, OFF_FF14);
    pack_w_kernel<<<(DEPTH*6*48  + 7) / 8, 256>>>(ff2_w, wh, wl, DDIM, FFN, OFF_FF24);
    mask_reset_kernel<<<1, 1>>>();
    mask_detect_kernel<<<(NROW + 255) / 256, 256>>>((const unsigned char*)mask);
    mask_expand_kernel<<<(NROW + 255) / 256, 256>>>(mask);

    for (int i = 0; i < DEPTH; i++) {
        attn_mma_kernel<<<gATT, 256, SMEM_ATT_BYTES>>>(qkvB, bppm, pair_w, pair_b,
                                                       relpos_w, relpos_b, aAh, aAl);
        gemm_pk_kernel<1><<<gOUT, 256>>>(aAh, aAl, WHI(i, OFF_OUT4), WLO(i, OFF_OUT4),
                                         out_b + i*DDIM, x, x, nullptr, nullptr,
                                         NROW, DDIM, DDIM, 0);
        ln_pack_kernel<<<NROW / 8, 256>>>(x, ln2_s + i*DDIM, ln2_b + i*DDIM, aAh, aAl);
        gemm_pk_kernel<2><<<gFF1, 256>>>(aAh, aAl, WHI(i, OFF_FF14), WLO(i, OFF_FF14),
                                         ff1_b + i*FFN, nullptr, nullptr, aBh, aBl,
                                         NROW, FFN, DDIM, 48);
        gemm_pk_kernel<1><<<gOUT, 256>>>(aBh, aBl, WHI(i, OFF_FF24), WLO(i, OFF_FF24),
                                         ff2_b + i*DDIM, x, x, nullptr, nullptr,
                                         NROW, DDIM, FFN, 0);
        if (i + 1 < DEPTH) {
            ln_pack_kernel<<<NROW / 8, 256>>>(x, ln1_s + (i+1)*DDIM, ln1_b + (i+1)*DDIM,
                                              aAh, aAl);
            gemm_pk_kernel<0><<<gQKV, 256>>>(aAh, aAl,
                                             WHI(i+1, OFF_QKV4), WLO(i+1, OFF_QKV4),
                                             qkv_b + (i+1)*QKVN, nullptr, qkvB,
                                             nullptr, nullptr, NROW, QKVN, DDIM, 0);
        }
    }

    proj_kernel<<<NROW / 8, 256>>>(x, proj_w, proj_b, out);
}

// round 17
// speedup vs baseline: 1.0594x; 1.0114x over previous
#include <cuda_runtime.h>
#include <cuda_bf16.h>
#include <math.h>
#include <stdint.h>

// ---------------- problem constants ----------------
#define BB   32
#define LL   512
#define DDIM 192
#define DEPTH 12
#define HH   6
#define DHH  32
#define KCLIP 32
#define BINS 65
#define NROW (BB*LL)          // 16384
#define QKVN (3*DDIM)         // 576
#define FFN  (4*DDIM)         // 768
#define SCALE_Q 0.17677669529663687f

// ---------------- scratch ----------------
__device__ float g_x  [NROW*DDIM];
__device__ float g_qkv[NROW*QKVN];
__device__ float g_maskf[NROW];
__device__ int   g_mask_is_u8;

// packed activation fragments (bf16 hi/lo words, mma-fragment layout)
#define APK_A_WORDS (NROW*DDIM/2)    // K=192 layout (NKB=12)
#define APK_B_WORDS (NROW*FFN/2)     // K=768 layout (NKB=48)
__device__ unsigned g_aA_hi[APK_A_WORDS], g_aA_lo[APK_A_WORDS];
__device__ unsigned g_aB_hi[APK_B_WORDS], g_aB_lo[APK_B_WORDS];

// packed weight fragments, all layers
#define WPK_L4 55296                 // uint4 per layer (qkv+out+ff1+ff2)
#define OFF_QKV4 0
#define OFF_OUT4 13824
#define OFF_FF14 18432
#define OFF_FF24 36864
__device__ unsigned g_w_hi[WPK_L4*DEPTH*4], g_w_lo[WPK_L4*DEPTH*4];

// ---------------- mask handling ----------------
__global__ void mask_reset_kernel() { g_mask_is_u8 = 0; }
__global__ void mask_detect_kernel(const unsigned char* __restrict__ m) {
    int i = blockIdx.x * 256 + threadIdx.x;
    if (i < NROW && (i & 3) != 0 && m[i] != 0) atomicOr(&g_mask_is_u8, 1);
}
__global__ void mask_expand_kernel(const void* __restrict__ m) {
    int i = blockIdx.x * 256 + threadIdx.x;
    if (i >= NROW) return;
    int v;
    if (g_mask_is_u8) v = ((const unsigned char*)m)[i];
    else              v = ((const int*)m)[i];
    g_maskf[i] = v ? 1.0f : 0.0f;
}

// ---------------- embedding ----------------
__global__ void embed_kernel(const int* __restrict__ seq,
                             const float* __restrict__ emb,
                             float* __restrict__ x) {
    int i = blockIdx.x * 256 + threadIdx.x;
    if (i >= NROW * DDIM) return;
    int row = i / DDIM, c = i - row * DDIM;
    x[i] = emb[seq[row] * DDIM + c];
}

// ---------------- bf16 helpers ----------------
__device__ __forceinline__ unsigned pack_bf16(float lo, float hi) {
    unsigned r;
    asm("cvt.rn.bf16x2.f32 %0, %1, %2;" : "=r"(r) : "f"(hi), "f"(lo));
    return r;
}
__device__ __forceinline__ unsigned lo_residual(unsigned hiw, float lo, float hi) {
    float h0 = __uint_as_float(hiw << 16);
    float h1 = __uint_as_float(hiw & 0xffff0000u);
    return pack_bf16(lo - h0, hi - h1);
}
__device__ __forceinline__ void mma_bf16v(float* c,
                                          unsigned a0, unsigned a1, unsigned a2, unsigned a3,
                                          unsigned b0, unsigned b1) {
    asm("mma.sync.aligned.m16n8k16.row.col.f32.bf16.bf16.f32 "
        "{%0,%1,%2,%3},{%4,%5,%6,%7},{%8,%9},{%0,%1,%2,%3};"
        : "+f"(c[0]), "+f"(c[1]), "+f"(c[2]), "+f"(c[3])
        : "r"(a0), "r"(a1), "r"(a2), "r"(a3), "r"(b0), "r"(b1));
}

// ---------------- layernorm + fragment pack (warp per row) ----------------
__global__ void ln_pack_kernel(const float* __restrict__ x,
                               const float* __restrict__ s, const float* __restrict__ bb,
                               unsigned* __restrict__ hi, unsigned* __restrict__ lo) {
    int row  = blockIdx.x * 8 + (threadIdx.x >> 5);
    int lane = threadIdx.x & 31;
    const float* xr = x + (size_t)row * DDIM;
    float2 v[3]; float sum = 0.f;
#pragma unroll
    for (int jj = 0; jj < 3; jj++) {
        v[jj] = *reinterpret_cast<const float2*>(xr + 2 * (lane + 32 * jj));
        sum += v[jj].x + v[jj].y;
    }
#pragma unroll
    for (int o = 16; o; o >>= 1) sum += __shfl_xor_sync(0xffffffffu, sum, o);
    float mu = sum * (1.0f / DDIM);
    float vs = 0.f;
#pragma unroll
    for (int jj = 0; jj < 3; jj++) {
        float d0 = v[jj].x - mu, d1 = v[jj].y - mu;
        vs += d0 * d0 + d1 * d1;
    }
#pragma unroll
    for (int o = 16; o; o >>= 1) vs += __shfl_xor_sync(0xffffffffu, vs, o);
    float inv = rsqrtf(vs * (1.0f / DDIM) + 1e-5f);

    int m16 = row >> 4, g8 = row & 7, hi8 = (row >> 3) & 1;
#pragma unroll
    for (int jj = 0; jj < 3; jj++) {
        int p = lane + 32 * jj;
        int kb = p >> 3, tgp = p & 3, cw = (p >> 2) & 1;
        float2 sv = *reinterpret_cast<const float2*>(s + 2 * p);
        float2 bv = *reinterpret_cast<const float2*>(bb + 2 * p);
        float f0 = (v[jj].x - mu) * inv * sv.x + bv.x;
        float f1 = (v[jj].y - mu) * inv * sv.y + bv.y;
        unsigned hw = pack_bf16(f0, f1);
        int idx = ((m16 * 12 + kb) * 32 + g8 * 4 + tgp) * 4 + hi8 + 2 * cw;
        hi[idx] = hw;
        lo[idx] = lo_residual(hw, f0, f1);
    }
}

// ---------------- weight fragment pack (warp per (layer, n32, kb)) ----------------
__global__ void pack_w_kernel(const float* __restrict__ W, unsigned* __restrict__ hiW,
                              unsigned* __restrict__ loW, int N, int K, int dstBase4) {
    int wid  = blockIdx.x * 8 + (threadIdx.x >> 5);
    int lane = threadIdx.x & 31, g = lane >> 2, tg = lane & 3;
    int NKB = K >> 4, perL = (N >> 5) * NKB;
    if (wid >= DEPTH * perL) return;
    int l = wid / perL, rem = wid - l * perL;
    int n32 = rem / NKB, kb = rem - n32 * NKB;
    const float* Wl = W + (size_t)l * N * K;
    unsigned wh[8], wl[8];
#pragma unroll
    for (int j = 0; j < 4; j++) {
        int n = n32 * 32 + j * 8 + g;
        const float* p = Wl + (size_t)n * K + kb * 16;
        float2 u = *reinterpret_cast<const float2*>(p + 2 * tg);
        float2 q = *reinterpret_cast<const float2*>(p + 8 + 2 * tg);
        wh[j*2]   = pack_bf16(u.x, u.y);
        wl[j*2]   = lo_residual(wh[j*2], u.x, u.y);
        wh[j*2+1] = pack_bf16(q.x, q.y);
        wl[j*2+1] = lo_residual(wh[j*2+1], q.x, q.y);
    }
    size_t o4 = (size_t)l * WPK_L4 + dstBase4 + (size_t)(n32 * NKB + kb) * 64 + lane;
    uint4* H = reinterpret_cast<uint4*>(hiW);
    uint4* L = reinterpret_cast<uint4*>(loW);
    H[o4]      = make_uint4(wh[0], wh[1], wh[2], wh[3]);
    H[o4 + 32] = make_uint4(wh[4], wh[5], wh[6], wh[7]);
    L[o4]      = make_uint4(wl[0], wl[1], wl[2], wl[3]);
    L[o4 + 32] = make_uint4(wl[4], wl[5], wl[6], wl[7]);
}

// ================= fragment-direct GEMM (no smem, no syncs) =================
// MODE 0: C=acc+bias (fp32)  1: C=acc+bias+res (fp32)  2: gelu(acc+bias) -> packed out
template <int MODE>
__global__ __launch_bounds__(256, 2)
void gemm_pk_kernel(const unsigned* __restrict__ AhiW, const unsigned* __restrict__ AloW,
                    const unsigned* __restrict__ BhiW, const unsigned* __restrict__ BloW,
                    const float* __restrict__ bias, const float* __restrict__ res,
                    float* __restrict__ C, unsigned* __restrict__ Phi, unsigned* __restrict__ Plo,
                    int M, int N, int K, int NKB_OUT) {
    const uint4* Ahi = reinterpret_cast<const uint4*>(AhiW);
    const uint4* Alo = reinterpret_cast<const uint4*>(AloW);
    const uint4* Bhi = reinterpret_cast<const uint4*>(BhiW);
    const uint4* Blo = reinterpret_cast<const uint4*>(BloW);

    const int tid = threadIdx.x, lane = tid & 31, wid = tid >> 5;
    const int g = lane >> 2, tg = lane & 3;
    const int wm = (wid & 3) * 32, wn = (wid >> 2) * 32;
    const int m0 = blockIdx.y * 128, n0 = blockIdx.x * 64;
    const int NKB = K >> 4;
    const size_t m16a = (size_t)((m0 + wm) >> 4);
    const size_t n32  = (size_t)((n0 + wn) >> 5);

    const uint4* pa0h = Ahi + m16a * NKB * 32 + lane;
    const uint4* pa1h = Ahi + (m16a + 1) * NKB * 32 + lane;
    const uint4* pa0l = Alo + m16a * NKB * 32 + lane;
    const uint4* pa1l = Alo + (m16a + 1) * NKB * 32 + lane;
    const uint4* pbh  = Bhi + n32 * NKB * 64 + lane;
    const uint4* pbl  = Blo + n32 * NKB * 64 + lane;

    float acc[2][4][4];
#pragma unroll
    for (int i = 0; i < 2; i++)
#pragma unroll
        for (int j = 0; j < 4; j++)
#pragma unroll
            for (int t = 0; t < 4; t++) acc[i][j][t] = 0.f;

    uint4 cA0h = pa0h[0], cA1h = pa1h[0], cA0l = pa0l[0], cA1l = pa1l[0];
    uint4 cB0h = pbh[0], cB1h = pbh[32], cB0l = pbl[0], cB1l = pbl[32];

    for (int kb = 0; kb < NKB; kb++) {
        uint4 nA0h, nA1h, nA0l, nA1l, nB0h, nB1h, nB0l, nB1l;
        if (kb + 1 < NKB) {
            int off = (kb + 1) * 32, offb = (kb + 1) * 64;
            nA0h = pa0h[off]; nA1h = pa1h[off];
            nA0l = pa0l[off]; nA1l = pa1l[off];
            nB0h = pbh[offb]; nB1h = pbh[offb + 32];
            nB0l = pbl[offb]; nB1l = pbl[offb + 32];
        }
        unsigned aH[2][4] = {{cA0h.x, cA0h.y, cA0h.z, cA0h.w},
                             {cA1h.x, cA1h.y, cA1h.z, cA1h.w}};
        unsigned aL[2][4] = {{cA0l.x, cA0l.y, cA0l.z, cA0l.w},
                             {cA1l.x, cA1l.y, cA1l.z, cA1l.w}};
        unsigned bH[2][4] = {{cB0h.x, cB0h.y, cB0h.z, cB0h.w},
                             {cB1h.x, cB1h.y, cB1h.z, cB1h.w}};
        unsigned bL[2][4] = {{cB0l.x, cB0l.y, cB0l.z, cB0l.w},
                             {cB1l.x, cB1l.y, cB1l.z, cB1l.w}};
#pragma unroll
        for (int mf = 0; mf < 2; mf++) {
#pragma unroll
            for (int nf = 0; nf < 4; nf++) {
                unsigned b0 = bH[nf >> 1][(nf & 1) * 2];
                unsigned b1 = bH[nf >> 1][(nf & 1) * 2 + 1];
                unsigned l0 = bL[nf >> 1][(nf & 1) * 2];
                unsigned l1 = bL[nf >> 1][(nf & 1) * 2 + 1];
                mma_bf16v(acc[mf][nf], aH[mf][0], aH[mf][1], aH[mf][2], aH[mf][3], b0, b1);
                mma_bf16v(acc[mf][nf], aH[mf][0], aH[mf][1], aH[mf][2], aH[mf][3], l0, l1);
                mma_bf16v(acc[mf][nf], aL[mf][0], aL[mf][1], aL[mf][2], aL[mf][3], b0, b1);
            }
        }
        cA0h = nA0h; cA1h = nA1h; cA0l = nA0l; cA1l = nA1l;
        cB0h = nB0h; cB1h = nB1h; cB0l = nB0l; cB1l = nB1l;
    }

    if (MODE == 2) {
#pragma unroll
        for (int mf = 0; mf < 2; mf++) {
            int m16o = ((m0 + wm) >> 4) + mf;
#pragma unroll
            for (int nf = 0; nf < 4; nf++) {
                int c = n0 + wn + nf * 8 + tg * 2;
                float2 bi = *reinterpret_cast<const float2*>(bias + c);
                int kb2 = (n0 >> 4) + (wn >> 4) + (nf >> 1);
                int cw  = nf & 1;
#pragma unroll
                for (int half = 0; half < 2; half++) {
                    float v0 = acc[mf][nf][half * 2 + 0] + bi.x;
                    float v1 = acc[mf][nf][half * 2 + 1] + bi.y;
                    v0 = 0.5f * v0 * (1.0f + erff(v0 * 0.7071067811865476f));
                    v1 = 0.5f * v1 * (1.0f + erff(v1 * 0.7071067811865476f));
                    unsigned hw = pack_bf16(v0, v1);
                    int idx = ((m16o * NKB_OUT + kb2) * 32 + g * 4 + tg) * 4 + half + 2 * cw;
                    Phi[idx] = hw;
                    Plo[idx] = lo_residual(hw, v0, v1);
                }
            }
        }
    } else {
#pragma unroll
        for (int mf = 0; mf < 2; mf++) {
            int r = m0 + wm + mf * 16 + g;
#pragma unroll
            for (int nf = 0; nf < 4; nf++) {
                int c = n0 + wn + nf * 8 + tg * 2;
                float2 bi = *reinterpret_cast<const float2*>(bias + c);
#pragma unroll
                for (int half = 0; half < 2; half++) {
                    int rr = r + half * 8;
                    float v0 = acc[mf][nf][half * 2 + 0] + bi.x;
                    float v1 = acc[mf][nf][half * 2 + 1] + bi.y;
                    if (MODE == 1) {
                        float2 rv = *reinterpret_cast<const float2*>(res + (size_t)rr * N + c);
                        v0 += rv.x; v1 += rv.y;
                    }
                    *reinterpret_cast<float2*>(C + (size_t)rr * N + c) = make_float2(v0, v1);
                }
            }
        }
    }
}

// ====== flash attention: 2-pass split, double-buffered K/V, 1 sync per kt ======
#define KQ_STRIDE 20
#define V_STRIDE  69
#define KBUF 2560              // words per K buffer (hi or lo)
#define VBUF 2208              // words per V buffer (32*69)
#define OFF_KH 0               // 2 x 2560
#define OFF_KL 5120            // 2 x 2560
#define OFF_VH 10240           // 2 x 2208
#define OFF_VL 14656           // 2 x 2208
#define OFF_QH 19072           // 2560
#define OFF_LUT 21632          // 1023
#define OFF_MSK (21632+1023)   // 512
#define SMEM_ATT_WORDS (21632+1023+512+9)
#define SMEM_ATT_BYTES (SMEM_ATT_WORDS*4)

__global__ __launch_bounds__(256, 2)
void attn_mma_kernel(const float* __restrict__ qkv, const float* __restrict__ bppm,
                     const float* __restrict__ pair_w, const float* __restrict__ pair_b,
                     const float* __restrict__ relpos_w, const float* __restrict__ relpos_b,
                     unsigned* __restrict__ oHi, unsigned* __restrict__ oLo) {
    extern __shared__ unsigned sm[];
    unsigned* KsH = sm + OFF_KH;
    unsigned* KsL = sm + OFF_KL;
    unsigned* VsH = sm + OFF_VH;
    unsigned* VsL = sm + OFF_VL;
    unsigned* QsH = sm + OFF_QH;
    float*    lut = (float*)(sm + OFF_LUT);
    float*    msk = (float*)(sm + OFF_MSK);

    const int tid  = threadIdx.x;
    const int lane = tid & 31;
    const int w    = tid >> 5;
    const int qt   = blockIdx.x;
    const int h    = blockIdx.y;
    const int b    = blockIdx.z;
    const int q0   = qt * 128;
    const int wq   = w * 16;
    const int g    = lane >> 2;
    const int tg   = lane & 3;

    // per-thread staging coordinates (loop-invariant)
    const int sr  = w * 16 + (lane >> 3);      // K row base (+ j*4)
    const int sc4 = (lane & 7) * 4;            // K col base
    const int vp  = w * 8 + (lane >> 3);       // V pair base (+ j*4)
    const int vd4 = (lane & 7) * 4;            // V dim base

    // ---- stage Q (scale folded; hi only) ----
#pragma unroll
    for (int j = 0; j < 4; j++) {
        int r = sr + j * 4;
        float4 v = *reinterpret_cast<const float4*>(
            qkv + (size_t)(b * LL + q0 + r) * QKVN + h * DHH + sc4);
        v.x *= SCALE_Q; v.y *= SCALE_Q; v.z *= SCALE_Q; v.w *= SCALE_Q;
        int base = r * KQ_STRIDE + (sc4 >> 1);
        QsH[base]     = pack_bf16(v.x, v.y);
        QsH[base + 1] = pack_bf16(v.z, v.w);
    }
    const float addc = pair_b[h] + relpos_b[h];
#pragma unroll
    for (int j = 0; j < 4; j++) {
        int i = j * 256 + tid;
        if (i < 1023) {
            int d = i - 511;
            int cd = min(KCLIP, max(-KCLIP, d)) + KCLIP;
            lut[i] = relpos_w[h * BINS + cd] + addc;
        }
    }
    for (int k = tid; k < LL; k += 256) msk[k] = g_maskf[b * LL + k];

    // ---- stage K/V tile 0 into buffer 0 ----
#pragma unroll
    for (int j = 0; j < 4; j++) {
        int r = sr + j * 4;
        float4 v = *reinterpret_cast<const float4*>(
            qkv + (size_t)(b * LL + r) * QKVN + DDIM + h * DHH + sc4);
        unsigned h0 = pack_bf16(v.x, v.y);
        unsigned h1 = pack_bf16(v.z, v.w);
        int base = r * KQ_STRIDE + (sc4 >> 1);
        KsH[base]     = h0;
        KsH[base + 1] = h1;
        KsL[base]     = lo_residual(h0, v.x, v.y);
        KsL[base + 1] = lo_residual(h1, v.z, v.w);
    }
#pragma unroll
    for (int j = 0; j < 2; j++) {
        int p = vp + j * 4;
        const float* basep = qkv + (size_t)(b * LL + 2 * p) * QKVN + 2 * DDIM + h * DHH + vd4;
        float4 v0 = *reinterpret_cast<const float4*>(basep);
        float4 v1 = *reinterpret_cast<const float4*>(basep + QKVN);
        float a0[4] = {v0.x, v0.y, v0.z, v0.w};
        float a1[4] = {v1.x, v1.y, v1.z, v1.w};
#pragma unroll
        for (int i = 0; i < 4; i++) {
            unsigned hw = pack_bf16(a0[i], a1[i]);
            VsH[(vd4 + i) * V_STRIDE + p] = hw;
            VsL[(vd4 + i) * V_STRIDE + p] = lo_residual(hw, a0[i], a1[i]);
        }
    }
    __syncthreads();

    // ---- hoist Q fragments ----
    unsigned qaH[2][4];
#pragma unroll
    for (int ks = 0; ks < 2; ks++) {
        int ab = (wq + g) * KQ_STRIDE + ks * 8 + tg;
        qaH[ks][0] = QsH[ab];       qaH[ks][1] = QsH[ab + 8 * KQ_STRIDE];
        qaH[ks][2] = QsH[ab + 4];   qaH[ks][3] = QsH[ab + 8 * KQ_STRIDE + 4];
    }

    const float pw = pair_w[h];
    float m0v = -1e30f, m1v = -1e30f;
    float lp0 = 0.f,   lp1 = 0.f;
    float Oacc[4][4];
#pragma unroll
    for (int i = 0; i < 4; i++)
#pragma unroll
        for (int j = 0; j < 4; j++) Oacc[i][j] = 0.f;

    const int row0 = q0 + wq + g;

    for (int kt = 0; kt < 4; kt++) {
        const int cur = kt & 1, nxt = cur ^ 1;
        const unsigned* KH = KsH + cur * KBUF;
        const unsigned* KL = KsL + cur * KBUF;
        const unsigned* VH = VsH + cur * VBUF;
        const unsigned* VL = VsL + cur * VBUF;
        const int k0 = kt * 128;

        // ---- S = Qhi·(Khi + Klo) on current buffer ----
        float S[16][4];
#pragma unroll
        for (int nt = 0; nt < 16; nt++)
#pragma unroll
            for (int c = 0; c < 4; c++) S[nt][c] = 0.f;

#pragma unroll
        for (int ks = 0; ks < 2; ks++) {
#pragma unroll
            for (int nt = 0; nt < 16; nt++) {
                int bb = (nt * 8 + g) * KQ_STRIDE + ks * 8 + tg;
                unsigned bH0 = KH[bb], bH1 = KH[bb + 4];
                unsigned bL0 = KL[bb], bL1 = KL[bb + 4];
                mma_bf16v(S[nt], qaH[ks][0], qaH[ks][1], qaH[ks][2], qaH[ks][3], bH0, bH1);
                mma_bf16v(S[nt], qaH[ks][0], qaH[ks][1], qaH[ks][2], qaH[ks][3], bL0, bL1);
            }
        }

        // ---- stage tile kt+1 into other buffer (overlaps tensor drain) ----
        if (kt < 3) {
            const int k1 = k0 + 128;
            unsigned* nKH = KsH + nxt * KBUF;
            unsigned* nKL = KsL + nxt * KBUF;
            unsigned* nVH = VsH + nxt * VBUF;
            unsigned* nVL = VsL + nxt * VBUF;
#pragma unroll
            for (int j = 0; j < 4; j++) {
                int r = sr + j * 4;
                float4 v = *reinterpret_cast<const float4*>(
                    qkv + (size_t)(b * LL + k1 + r) * QKVN + DDIM + h * DHH + sc4);
                unsigned h0 = pack_bf16(v.x, v.y);
                unsigned h1 = pack_bf16(v.z, v.w);
                int base = r * KQ_STRIDE + (sc4 >> 1);
                nKH[base]     = h0;
                nKH[base + 1] = h1;
                nKL[base]     = lo_residual(h0, v.x, v.y);
                nKL[base + 1] = lo_residual(h1, v.z, v.w);
            }
#pragma unroll
            for (int j = 0; j < 2; j++) {
                int p = vp + j * 4;
                const float* basep = qkv + (size_t)(b * LL + k1 + 2 * p) * QKVN + 2 * DDIM + h * DHH + vd4;
                float4 v0 = *reinterpret_cast<const float4*>(basep);
                float4 v1 = *reinterpret_cast<const float4*>(basep + QKVN);
                float a0[4] = {v0.x, v0.y, v0.z, v0.w};
                float a1[4] = {v1.x, v1.y, v1.z, v1.w};
#pragma unroll
                for (int i = 0; i < 4; i++) {
                    unsigned hw = pack_bf16(a0[i], a1[i]);
                    nVH[(vd4 + i) * V_STRIDE + p] = hw;
                    nVL[(vd4 + i) * V_STRIDE + p] = lo_residual(hw, a0[i], a1[i]);
                }
            }
        }

        // ---- bias + mask ----
#pragma unroll
        for (int nt = 0; nt < 16; nt++) {
            int col = k0 + nt * 8 + tg * 2;
            float2 bp0 = *reinterpret_cast<const float2*>(
                bppm + ((size_t)(b * LL + row0)) * LL + col);
            float2 bp1 = *reinterpret_cast<const float2*>(
                bppm + ((size_t)(b * LL + row0 + 8)) * LL + col);
            int i00 = row0 - col + 511;
            float mk0 = msk[col], mk1 = msk[col + 1];
            float s0 = S[nt][0] + bp0.x * pw + lut[i00];
            float s1 = S[nt][1] + bp0.y * pw + lut[i00 - 1];
            float s2 = S[nt][2] + bp1.x * pw + lut[i00 + 8];
            float s3 = S[nt][3] + bp1.y * pw + lut[i00 + 7];
            S[nt][0] = (mk0 != 0.f) ? s0 : -1e9f;
            S[nt][1] = (mk1 != 0.f) ? s1 : -1e9f;
            S[nt][2] = (mk0 != 0.f) ? s2 : -1e9f;
            S[nt][3] = (mk1 != 0.f) ? s3 : -1e9f;
        }

        // ---- online softmax ----
        float t0 = -1e30f, t1 = -1e30f;
#pragma unroll
        for (int nt = 0; nt < 16; nt++) {
            t0 = fmaxf(t0, fmaxf(S[nt][0], S[nt][1]));
            t1 = fmaxf(t1, fmaxf(S[nt][2], S[nt][3]));
        }
        t0 = fmaxf(t0, __shfl_xor_sync(0xffffffffu, t0, 1));
        t0 = fmaxf(t0, __shfl_xor_sync(0xffffffffu, t0, 2));
        t1 = fmaxf(t1, __shfl_xor_sync(0xffffffffu, t1, 1));
        t1 = fmaxf(t1, __shfl_xor_sync(0xffffffffu, t1, 2));

        float mn0 = fmaxf(m0v, t0), mn1 = fmaxf(m1v, t1);
        float al0 = __expf(m0v - mn0), al1 = __expf(m1v - mn1);
        m0v = mn0; m1v = mn1;

        float sum0 = 0.f, sum1 = 0.f;
#pragma unroll
        for (int nt = 0; nt < 16; nt++) {
            S[nt][0] = __expf(S[nt][0] - m0v);
            S[nt][1] = __expf(S[nt][1] - m0v);
            S[nt][2] = __expf(S[nt][2] - m1v);
            S[nt][3] = __expf(S[nt][3] - m1v);
            sum0 += S[nt][0] + S[nt][1];
            sum1 += S[nt][2] + S[nt][3];
        }
        lp0 = lp0 * al0 + sum0;
        lp1 = lp1 * al1 + sum1;
#pragma unroll
        for (int nt = 0; nt < 4; nt++) {
            Oacc[nt][0] *= al0; Oacc[nt][1] *= al0;
            Oacc[nt][2] *= al1; Oacc[nt][3] *= al1;
        }

        // ---- O += Phi·(Vhi + Vlo) on current buffer ----
#pragma unroll
        for (int j = 0; j < 8; j++) {
            unsigned pH0 = pack_bf16(S[2*j][0],   S[2*j][1]);
            unsigned pH1 = pack_bf16(S[2*j][2],   S[2*j][3]);
            unsigned pH2 = pack_bf16(S[2*j+1][0], S[2*j+1][1]);
            unsigned pH3 = pack_bf16(S[2*j+1][2], S[2*j+1][3]);
#pragma unroll
            for (int nt = 0; nt < 4; nt++) {
                int bb = (nt * 8 + g) * V_STRIDE + j * 8 + tg;
                unsigned bH0 = VH[bb], bH1 = VH[bb + 4];
                unsigned bL0 = VL[bb], bL1 = VL[bb + 4];
                mma_bf16v(Oacc[nt], pH0, pH1, pH2, pH3, bH0, bH1);
                mma_bf16v(Oacc[nt], pH0, pH1, pH2, pH3, bL0, bL1);
            }
        }
        __syncthreads();
    }

    float l0 = lp0 + __shfl_xor_sync(0xffffffffu, lp0, 1);
    l0 += __shfl_xor_sync(0xffffffffu, l0, 2);
    float l1 = lp1 + __shfl_xor_sync(0xffffffffu, lp1, 1);
    l1 += __shfl_xor_sync(0xffffffffu, l1, 2);
    float inv0 = 1.0f / l0, inv1 = 1.0f / l1;

    // ---- packed-fragment epilogue (GLOBAL row: b*LL + row0) ----
    int m16 = (b * LL + row0) >> 4;
#pragma unroll
    for (int nt = 0; nt < 4; nt++) {
        int kb = 2 * h + (nt >> 1);
        int cw = nt & 1;
        float f0 = Oacc[nt][0] * inv0, f1 = Oacc[nt][1] * inv0;
        float f2 = Oacc[nt][2] * inv1, f3 = Oacc[nt][3] * inv1;
        int base = ((m16 * 12 + kb) * 32 + g * 4 + tg) * 4 + 2 * cw;
        unsigned hw0 = pack_bf16(f0, f1);
        unsigned hw1 = pack_bf16(f2, f3);
        oHi[base]     = hw0;
        oLo[base]     = lo_residual(hw0, f0, f1);
        oHi[base + 1] = hw1;
        oLo[base + 1] = lo_residual(hw1, f2, f3);
    }
}

// ---------------- final projection ----------------
__global__ void proj_kernel(const float* __restrict__ x,
                            const float* __restrict__ pw,
                            const float* __restrict__ pb,
                            float* __restrict__ out) {
    int row  = blockIdx.x * 8 + (threadIdx.x >> 5);
    int lane = threadIdx.x & 31;
    const float* xr = x + (size_t)row * DDIM;
    float d0 = 0.f, d1 = 0.f;
#pragma unroll
    for (int j = 0; j < 6; j++) {
        int c = lane + 32*j;
        float v = xr[c];
        d0 += v * pw[c];
        d1 += v * pw[DDIM + c];
    }
#pragma unroll
    for (int o = 16; o; o >>= 1) {
        d0 += __shfl_xor_sync(0xffffffffu, d0, o);
        d1 += __shfl_xor_sync(0xffffffffu, d1, o);
    }
    if (lane == 0) {
        out[row*2 + 0] = d0 + pb[0];
        out[row*2 + 1] = d1 + pb[1];
    }
}

// ---------------- launch ----------------
extern "C" void kernel_launch(void* const* d_in, const int* in_sizes, int n_in,
                              void* d_out, int out_size) {
    const int*   seq      = (const int*)  d_in[0];
    const void*  mask     =               d_in[1];
    const float* bppm     = (const float*)d_in[2];
    const float* emb      = (const float*)d_in[3];
    const float* pair_w   = (const float*)d_in[4];
    const float* pair_b   = (const float*)d_in[5];
    const float* relpos_w = (const float*)d_in[6];
    const float* relpos_b = (const float*)d_in[7];
    const float* ln1_s    = (const float*)d_in[8];
    const float* ln1_b    = (const float*)d_in[9];
    const float* qkv_w    = (const float*)d_in[10];
    const float* qkv_b    = (const float*)d_in[11];
    const float* out_w    = (const float*)d_in[12];
    const float* out_b    = (const float*)d_in[13];
    const float* ln2_s    = (const float*)d_in[14];
    const float* ln2_b    = (const float*)d_in[15];
    const float* ff1_w    = (const float*)d_in[16];
    const float* ff1_b    = (const float*)d_in[17];
    const float* ff2_w    = (const float*)d_in[18];
    const float* ff2_b    = (const float*)d_in[19];
    const float* proj_w   = (const float*)d_in[20];
    const float* proj_b   = (const float*)d_in[21];
    float* out = (float*)d_out;

    float *x, *qkvB;
    unsigned *aAh, *aAl, *aBh, *aBl, *wh, *wl;
    cudaGetSymbolAddress((void**)&x,    g_x);
    cudaGetSymbolAddress((void**)&qkvB, g_qkv);
    cudaGetSymbolAddress((void**)&aAh,  g_aA_hi);
    cudaGetSymbolAddress((void**)&aAl,  g_aA_lo);
    cudaGetSymbolAddress((void**)&aBh,  g_aB_hi);
    cudaGetSymbolAddress((void**)&aBl,  g_aB_lo);
    cudaGetSymbolAddress((void**)&wh,   g_w_hi);
    cudaGetSymbolAddress((void**)&wl,   g_w_lo);

    static int attr_set = 0;
    if (!attr_set) {
        cudaFuncSetAttribute(attn_mma_kernel,
                             cudaFuncAttributeMaxDynamicSharedMemorySize, SMEM_ATT_BYTES);
        attr_set = 1;
    }

    auto WHI = [&](int layer, int off4) { return wh + ((size_t)layer * WPK_L4 + off4) * 4; };
    auto WLO = [&](int layer, int off4) { return wl + ((size_t)layer * WPK_L4 + off4) * 4; };

    dim3 gQKV(QKVN / 64, NROW / 128);   // 9 x 128
    dim3 gOUT(DDIM / 64, NROW / 128);   // 3 x 128
    dim3 gFF1(FFN  / 64, NROW / 128);   // 12 x 128
    dim3 gATT(LL / 128, HH, BB);        // 4 x 6 x 32

    // ---- launch order keeps gemm<0> at slot 3 ----
    embed_kernel<<<(NROW * DDIM) / 256, 256>>>(seq, emb, x);                       // 0
    ln_pack_kernel<<<NROW / 8, 256>>>(x, ln1_s, ln1_b, aAh, aAl);                  // 1
    pack_w_kernel<<<(DEPTH*18*12 + 7) / 8, 256>>>(qkv_w, wh, wl, QKVN, DDIM, OFF_QKV4);  // 2
    gemm_pk_kernel<0><<<gQKV, 256>>>(aAh, aAl, WHI(0, OFF_QKV4), WLO(0, OFF_QKV4), // 3 (profiled)
                                     qkv_b, nullptr, qkvB, nullptr, nullptr,
                                     NROW, QKVN, DDIM, 0);
    pack_w_kernel<<<(DEPTH*6*12  + 7) / 8, 256>>>(out_w, wh, wl, DDIM, DDIM, OFF_OUT4);
    pack_w_kernel<<<(DEPTH*24*12 + 7) / 8, 256>>>(ff1_w, wh, wl, FFN, DDIM, OFF_FF14);
    pack_w_kernel<<<(DEPTH*6*48  + 7) / 8, 256>>>(ff2_w, wh, wl, DDIM, FFN, OFF_FF24);
    mask_reset_kernel<<<1, 1>>>();
    mask_detect_kernel<<<(NROW + 255) / 256, 256>>>((const unsigned char*)mask);
    mask_expand_kernel<<<(NROW + 255) / 256, 256>>>(mask);

    for (int i = 0; i < DEPTH; i++) {
        attn_mma_kernel<<<gATT, 256, SMEM_ATT_BYTES>>>(qkvB, bppm, pair_w, pair_b,
                                                       relpos_w, relpos_b, aAh, aAl);
        gemm_pk_kernel<1><<<gOUT, 256>>>(aAh, aAl, WHI(i, OFF_OUT4), WLO(i, OFF_OUT4),
                                         out_b + i*DDIM, x, x, nullptr, nullptr,
                                         NROW, DDIM, DDIM, 0);
        ln_pack_kernel<<<NROW / 8, 256>>>(x, ln2_s + i*DDIM, ln2_b + i*DDIM, aAh, aAl);
        gemm_pk_kernel<2><<<gFF1, 256>>>(aAh, aAl, WHI(i, OFF_FF14), WLO(i, OFF_FF14),
                                         ff1_b + i*FFN, nullptr, nullptr, aBh, aBl,
                                         NROW, FFN, DDIM, 48);
        gemm_pk_kernel<1><<<gOUT, 256>>>(aBh, aBl, WHI(i, OFF_FF24), WLO(i, OFF_FF24),
                                         ff2_b + i*DDIM, x, x, nullptr, nullptr,
                                         NROW, DDIM, FFN, 0);
        if (i + 1 < DEPTH) {
            ln_pack_kernel<<<NROW / 8, 256>>>(x, ln1_s + (i+1)*DDIM, ln1_b + (i+1)*DDIM,
                                              aAh, aAl);
            gemm_pk_kernel<0><<<gQKV, 256>>>(aAh, aAl,
                                             WHI(i+1, OFF_QKV4), WLO(i+1, OFF_QKV4),
                                             qkv_b + (i+1)*QKVN, nullptr, qkvB,
                                             nullptr, nullptr, NROW, QKVN, DDIM, 0);
        }
    }

    proj_kernel<<<NROW / 8, 256>>>(x, proj_w, proj_b, out);
}